// round 7
// baseline (speedup 1.0000x reference)
#include <cuda_runtime.h>
#include <math.h>

#define NTOK 4096
#define HDIM 1024
#define FDIM 4096
#define NE   8

// ---------------- device scratch (no allocations allowed) ----------------
__device__ int   g_count[NE];
__device__ int   g_off[NE];
__device__ int   g_tok[NE * NTOK];
__device__ float g_wt[NE * NTOK];
__device__ float g_zsq[NTOK];
__device__ float g_wa[NTOK];   // top-1 softmax prob
__device__ float g_wb[NTOK];   // top-2 softmax prob
__device__ float g_ma[NTOK];   // mask for "class 0" (one_hot(num_classes=2) quirk)
__device__ float g_mb[NTOK];   // mask for "class 1"
__device__ __align__(16) float g_h1[(size_t)2 * NTOK * FDIM];  // 128 MiB hidden scratch

typedef unsigned long long u64;

__device__ __forceinline__ u64 pk2(float lo, float hi) {
    u64 r; asm("mov.b64 %0, {%1,%2};" : "=l"(r) : "f"(lo), "f"(hi)); return r;
}
__device__ __forceinline__ void fma2(u64& c, u64 a, u64 b) {
    asm("fma.rn.f32x2 %0, %1, %2, %0;" : "+l"(c) : "l"(a), "l"(b));
}
__device__ __forceinline__ float2 unpk(u64 v) {
    float2 f; asm("mov.b64 {%0,%1}, %2;" : "=f"(f.x), "=f"(f.y) : "l"(v)); return f;
}
__device__ __forceinline__ float silu_f(float v) {
    return v / (1.0f + expf(-v));
}

// ---------------- small kernels ----------------
__global__ void zero_kernel(float* out, int n) {
    for (int i = blockIdx.x * blockDim.x + threadIdx.x; i < n; i += gridDim.x * blockDim.x)
        out[i] = 0.0f;
}

__global__ void reset_kernel() {
    if (threadIdx.x < NE) g_count[threadIdx.x] = 0;
}

// One warp per token: router logits, softmax, top-2, stats, scatter.
__global__ void router_kernel(const float* __restrict__ x, const float* __restrict__ gw) {
    int warp = threadIdx.x >> 5;
    int lane = threadIdx.x & 31;
    int t = blockIdx.x * (blockDim.x >> 5) + warp;
    if (t >= NTOK) return;

    float p[NE];
#pragma unroll
    for (int e = 0; e < NE; e++) p[e] = 0.0f;

    const float* xr = x + (size_t)t * HDIM;
    for (int h = lane; h < HDIM; h += 32) {
        float xv = xr[h];
#pragma unroll
        for (int e = 0; e < NE; e++) p[e] += xv * gw[e * HDIM + h];
    }
#pragma unroll
    for (int e = 0; e < NE; e++) {
#pragma unroll
        for (int s = 16; s > 0; s >>= 1) p[e] += __shfl_xor_sync(0xffffffffu, p[e], s);
    }

    if (lane == 0) {
        float m = p[0];
#pragma unroll
        for (int e = 1; e < NE; e++) m = fmaxf(m, p[e]);
        float Z = 0.0f;
        float pr[NE];
#pragma unroll
        for (int e = 0; e < NE; e++) { pr[e] = expf(p[e] - m); Z += pr[e]; }
        float invZ = 1.0f / Z;
#pragma unroll
        for (int e = 0; e < NE; e++) pr[e] *= invZ;

        // top-2 (strict >: lowest index wins ties, matching jax top_k)
        int e1 = 0; float v1 = pr[0];
#pragma unroll
        for (int e = 1; e < NE; e++) if (pr[e] > v1) { v1 = pr[e]; e1 = e; }
        int e2 = -1; float v2 = -1.0f;
#pragma unroll
        for (int e = 0; e < NE; e++) if (e != e1 && pr[e] > v2) { v2 = pr[e]; e2 = e; }

        float s  = v1 + v2;
        float r1 = v1 / s, r2 = v2 / s;

        float lse = m + logf(Z);
        g_zsq[t] = lse * lse;
        g_wa[t]  = v1;
        g_wb[t]  = v2;
        g_ma[t]  = (e1 == 0 || e2 == 0) ? 1.0f : 0.0f;
        g_mb[t]  = (e1 == 1 || e2 == 1) ? 1.0f : 0.0f;

        int s1 = atomicAdd(&g_count[e1], 1);
        g_tok[e1 * NTOK + s1] = t; g_wt[e1 * NTOK + s1] = r1;
        int s2 = atomicAdd(&g_count[e2], 1);
        g_tok[e2 * NTOK + s2] = t; g_wt[e2 * NTOK + s2] = r2;
    }
}

// Single block: losses + prefix offsets.
__global__ void finalize_kernel(float* out, int out_size) {
    int tid = threadIdx.x;
    float s[5] = {0, 0, 0, 0, 0};
    for (int i = tid; i < NTOK; i += 256) {
        s[0] += g_zsq[i]; s[1] += g_wa[i]; s[2] += g_wb[i];
        s[3] += g_ma[i];  s[4] += g_mb[i];
    }
    __shared__ float red[256];
    __shared__ float tot[5];
#pragma unroll
    for (int q = 0; q < 5; q++) {
        red[tid] = s[q];
        __syncthreads();
        for (int st = 128; st > 0; st >>= 1) {
            if (tid < st) red[tid] += red[tid + st];
            __syncthreads();
        }
        if (tid == 0) tot[q] = red[0];
        __syncthreads();
    }
    if (tid == 0) {
        const float invT = 1.0f / (float)NTOK;
        float zl  = tot[0] * invT;
        float aux = 2.0f * ((tot[3] * invT) * (tot[1] * invT) +
                            (tot[4] * invT) * (tot[2] * invT));
        long long base = (long long)NTOK * HDIM;
        if ((long long)out_size > base)     out[base]     = zl;
        if ((long long)out_size > base + 1) out[base + 1] = aux;
        int o = 0;
        for (int e = 0; e < NE; e++) { g_off[e] = o; o += g_count[e]; }
    }
}

// ---------------- grouped GEMMs ----------------
// Tile: BM=128, BN=64, BK=16, 256 threads, 8x4 micro-tile, f32x2 FMA.

__global__ void __launch_bounds__(256)
gemm1_kernel(const float* __restrict__ x, const float* __restrict__ w1,
             const float* __restrict__ b1) {
    int e = blockIdx.z;
    int cnt = g_count[e];
    int m0 = blockIdx.y * 128;
    if (m0 >= cnt) return;
    int n0 = blockIdx.x * 64;

    __shared__ __align__(16) float As[16][132];
    __shared__ __align__(16) float Bs[16][64];
    __shared__ int toks[128];

    int tid = threadIdx.x;
    for (int i = tid; i < 128; i += 256) {
        int r = m0 + i; if (r > cnt - 1) r = cnt - 1;
        toks[i] = g_tok[e * NTOK + r];
    }
    __syncthreads();

    const float* Bp = w1 + (size_t)e * HDIM * FDIM + n0;
    int ar = tid >> 2, ac = (tid & 3) << 2;
    int bk = tid >> 4, bc = (tid & 15) << 2;

    const float* Arow0 = x + (size_t)toks[ar] * HDIM + ac;
    const float* Arow1 = x + (size_t)toks[ar + 64] * HDIM + ac;

    float4 a0 = *(const float4*)(Arow0);
    float4 a1 = *(const float4*)(Arow1);
    float4 bv = *(const float4*)(Bp + (size_t)bk * FDIM + bc);

    u64 c2[4][4];
#pragma unroll
    for (int j = 0; j < 4; j++)
#pragma unroll
        for (int n = 0; n < 4; n++) c2[j][n] = 0ull;

    int tx = tid & 15, ty = tid >> 4;
    const int NKT = HDIM / 16;

    for (int kt = 0; kt < NKT; ++kt) {
        As[ac + 0][ar] = a0.x; As[ac + 1][ar] = a0.y;
        As[ac + 2][ar] = a0.z; As[ac + 3][ar] = a0.w;
        As[ac + 0][ar + 64] = a1.x; As[ac + 1][ar + 64] = a1.y;
        As[ac + 2][ar + 64] = a1.z; As[ac + 3][ar + 64] = a1.w;
        *(float4*)&Bs[bk][bc] = bv;
        __syncthreads();

        if (kt + 1 < NKT) {
            int k0 = (kt + 1) * 16;
            a0 = *(const float4*)(Arow0 + k0);
            a1 = *(const float4*)(Arow1 + k0);
            bv = *(const float4*)(Bp + (size_t)(k0 + bk) * FDIM + bc);
        }

#pragma unroll
        for (int kk = 0; kk < 16; kk++) {
            const u64* ap = (const u64*)&As[kk][ty * 8];
            u64 a2_0 = ap[0], a2_1 = ap[1], a2_2 = ap[2], a2_3 = ap[3];
            float4 b4 = *(const float4*)&Bs[kk][tx * 4];
            u64 bb0 = pk2(b4.x, b4.x), bb1 = pk2(b4.y, b4.y);
            u64 bb2 = pk2(b4.z, b4.z), bb3 = pk2(b4.w, b4.w);
            fma2(c2[0][0], a2_0, bb0); fma2(c2[0][1], a2_0, bb1);
            fma2(c2[0][2], a2_0, bb2); fma2(c2[0][3], a2_0, bb3);
            fma2(c2[1][0], a2_1, bb0); fma2(c2[1][1], a2_1, bb1);
            fma2(c2[1][2], a2_1, bb2); fma2(c2[1][3], a2_1, bb3);
            fma2(c2[2][0], a2_2, bb0); fma2(c2[2][1], a2_2, bb1);
            fma2(c2[2][2], a2_2, bb2); fma2(c2[2][3], a2_2, bb3);
            fma2(c2[3][0], a2_3, bb0); fma2(c2[3][1], a2_3, bb1);
            fma2(c2[3][2], a2_3, bb2); fma2(c2[3][3], a2_3, bb3);
        }
        __syncthreads();
    }

    int off = g_off[e];
    const float* bbp = b1 + e * FDIM + n0 + tx * 4;
    float bias0 = bbp[0], bias1 = bbp[1], bias2 = bbp[2], bias3 = bbp[3];

#pragma unroll
    for (int j = 0; j < 4; j++) {
        float2 cc0 = unpk(c2[j][0]), cc1 = unpk(c2[j][1]);
        float2 cc2 = unpk(c2[j][2]), cc3 = unpk(c2[j][3]);
        int mA = m0 + ty * 8 + 2 * j;
        int mB = mA + 1;
        if (mA < cnt) {
            float4 v;
            v.x = silu_f(cc0.x + bias0); v.y = silu_f(cc1.x + bias1);
            v.z = silu_f(cc2.x + bias2); v.w = silu_f(cc3.x + bias3);
            *(float4*)&g_h1[(size_t)(off + mA) * FDIM + n0 + tx * 4] = v;
        }
        if (mB < cnt) {
            float4 v;
            v.x = silu_f(cc0.y + bias0); v.y = silu_f(cc1.y + bias1);
            v.z = silu_f(cc2.y + bias2); v.w = silu_f(cc3.y + bias3);
            *(float4*)&g_h1[(size_t)(off + mB) * FDIM + n0 + tx * 4] = v;
        }
    }
}

__global__ void __launch_bounds__(256)
gemm2_kernel(const float* __restrict__ w2, const float* __restrict__ b2,
             float* __restrict__ out) {
    int e = blockIdx.z;
    int cnt = g_count[e];
    int m0 = blockIdx.y * 128;
    if (m0 >= cnt) return;
    int n0 = blockIdx.x * 64;
    int off = g_off[e];

    __shared__ __align__(16) float As[16][132];
    __shared__ __align__(16) float Bs[16][64];

    int tid = threadIdx.x;
    int ar = tid >> 2, ac = (tid & 3) << 2;
    int bk = tid >> 4, bc = (tid & 15) << 2;

    int r0 = min(m0 + ar, cnt - 1);
    int r1 = min(m0 + ar + 64, cnt - 1);
    const float* Arow0 = g_h1 + (size_t)(off + r0) * FDIM + ac;
    const float* Arow1 = g_h1 + (size_t)(off + r1) * FDIM + ac;
    const float* Bp = w2 + (size_t)e * FDIM * HDIM + n0;

    float4 a0 = *(const float4*)(Arow0);
    float4 a1 = *(const float4*)(Arow1);
    float4 bv = *(const float4*)(Bp + (size_t)bk * HDIM + bc);

    u64 c2[4][4];
#pragma unroll
    for (int j = 0; j < 4; j++)
#pragma unroll
        for (int n = 0; n < 4; n++) c2[j][n] = 0ull;

    int tx = tid & 15, ty = tid >> 4;
    const int NKT = FDIM / 16;

    for (int kt = 0; kt < NKT; ++kt) {
        As[ac + 0][ar] = a0.x; As[ac + 1][ar] = a0.y;
        As[ac + 2][ar] = a0.z; As[ac + 3][ar] = a0.w;
        As[ac + 0][ar + 64] = a1.x; As[ac + 1][ar + 64] = a1.y;
        As[ac + 2][ar + 64] = a1.z; As[ac + 3][ar + 64] = a1.w;
        *(float4*)&Bs[bk][bc] = bv;
        __syncthreads();

        if (kt + 1 < NKT) {
            int k0 = (kt + 1) * 16;
            a0 = *(const float4*)(Arow0 + k0);
            a1 = *(const float4*)(Arow1 + k0);
            bv = *(const float4*)(Bp + (size_t)(k0 + bk) * HDIM + bc);
        }

#pragma unroll
        for (int kk = 0; kk < 16; kk++) {
            const u64* ap = (const u64*)&As[kk][ty * 8];
            u64 a2_0 = ap[0], a2_1 = ap[1], a2_2 = ap[2], a2_3 = ap[3];
            float4 b4 = *(const float4*)&Bs[kk][tx * 4];
            u64 bb0 = pk2(b4.x, b4.x), bb1 = pk2(b4.y, b4.y);
            u64 bb2 = pk2(b4.z, b4.z), bb3 = pk2(b4.w, b4.w);
            fma2(c2[0][0], a2_0, bb0); fma2(c2[0][1], a2_0, bb1);
            fma2(c2[0][2], a2_0, bb2); fma2(c2[0][3], a2_0, bb3);
            fma2(c2[1][0], a2_1, bb0); fma2(c2[1][1], a2_1, bb1);
            fma2(c2[1][2], a2_1, bb2); fma2(c2[1][3], a2_1, bb3);
            fma2(c2[2][0], a2_2, bb0); fma2(c2[2][1], a2_2, bb1);
            fma2(c2[2][2], a2_2, bb2); fma2(c2[2][3], a2_2, bb3);
            fma2(c2[3][0], a2_3, bb0); fma2(c2[3][1], a2_3, bb1);
            fma2(c2[3][2], a2_3, bb2); fma2(c2[3][3], a2_3, bb3);
        }
        __syncthreads();
    }

    const float* bbp = b2 + e * HDIM + n0 + tx * 4;
    float bias0 = bbp[0], bias1 = bbp[1], bias2 = bbp[2], bias3 = bbp[3];

#pragma unroll
    for (int j = 0; j < 4; j++) {
        float2 cc0 = unpk(c2[j][0]), cc1 = unpk(c2[j][1]);
        float2 cc2 = unpk(c2[j][2]), cc3 = unpk(c2[j][3]);
        int mA = m0 + ty * 8 + 2 * j;
        int mB = mA + 1;
        int colb = n0 + tx * 4;
        if (mA < cnt) {
            int tok = g_tok[e * NTOK + mA];
            float wt = g_wt[e * NTOK + mA];
            float* op = out + (size_t)tok * HDIM + colb;
            atomicAdd(op + 0, wt * (cc0.x + bias0));
            atomicAdd(op + 1, wt * (cc1.x + bias1));
            atomicAdd(op + 2, wt * (cc2.x + bias2));
            atomicAdd(op + 3, wt * (cc3.x + bias3));
        }
        if (mB < cnt) {
            int tok = g_tok[e * NTOK + mB];
            float wt = g_wt[e * NTOK + mB];
            float* op = out + (size_t)tok * HDIM + colb;
            atomicAdd(op + 0, wt * (cc0.y + bias0));
            atomicAdd(op + 1, wt * (cc1.y + bias1));
            atomicAdd(op + 2, wt * (cc2.y + bias2));
            atomicAdd(op + 3, wt * (cc3.y + bias3));
        }
    }
}

// ---------------- launch ----------------
extern "C" void kernel_launch(void* const* d_in, const int* in_sizes, int n_in,
                              void* d_out, int out_size) {
    const float* x  = (const float*)d_in[0];
    const float* gw = (const float*)d_in[1];
    const float* w1 = (const float*)d_in[2];
    const float* b1 = (const float*)d_in[3];
    const float* w2 = (const float*)d_in[4];
    const float* b2 = (const float*)d_in[5];
    float* out = (float*)d_out;

    zero_kernel<<<2048, 256>>>(out, out_size);
    reset_kernel<<<1, 32>>>();
    router_kernel<<<NTOK / 8, 256>>>(x, gw);
    finalize_kernel<<<1, 256>>>(out, out_size);
    gemm1_kernel<<<dim3(FDIM / 64, NTOK / 128, NE), 256>>>(x, w1, b1);
    gemm2_kernel<<<dim3(HDIM / 64, NTOK / 128, NE), 256>>>(w2, b2, out);
}

// round 8
// speedup vs baseline: 1.0005x; 1.0005x over previous
#include <cuda_runtime.h>
#include <math.h>

#define NTOK 4096
#define HDIM 1024
#define FDIM 4096
#define NE   8

// ---------------- device scratch (no allocations allowed) ----------------
__device__ int   g_count[NE];
__device__ int   g_off[NE];
__device__ int   g_tok[NE * NTOK];
__device__ float g_wt[NE * NTOK];
__device__ float g_zsq[NTOK];
__device__ float g_wa[NTOK];   // top-1 softmax prob
__device__ float g_wb[NTOK];   // top-2 softmax prob
__device__ float g_ma[NTOK];   // mask for "class 0" (one_hot(num_classes=2) quirk)
__device__ float g_mb[NTOK];   // mask for "class 1"
__device__ __align__(16) float g_h1[(size_t)2 * NTOK * FDIM];  // 128 MiB hidden scratch

typedef unsigned long long u64;

__device__ __forceinline__ u64 pk2(float lo, float hi) {
    u64 r; asm("mov.b64 %0, {%1,%2};" : "=l"(r) : "f"(lo), "f"(hi)); return r;
}
__device__ __forceinline__ void fma2(u64& c, u64 a, u64 b) {
    asm("fma.rn.f32x2 %0, %1, %2, %0;" : "+l"(c) : "l"(a), "l"(b));
}
__device__ __forceinline__ float2 unpk(u64 v) {
    float2 f; asm("mov.b64 {%0,%1}, %2;" : "=f"(f.x), "=f"(f.y) : "l"(v)); return f;
}
__device__ __forceinline__ float silu_f(float v) {
    return v / (1.0f + expf(-v));
}

// ---------------- small kernels ----------------
__global__ void zero_kernel(float* out, int n) {
    for (int i = blockIdx.x * blockDim.x + threadIdx.x; i < n; i += gridDim.x * blockDim.x)
        out[i] = 0.0f;
}

__global__ void reset_kernel() {
    if (threadIdx.x < NE) g_count[threadIdx.x] = 0;
}

// One warp per token: router logits, softmax, top-2, stats, scatter.
__global__ void router_kernel(const float* __restrict__ x, const float* __restrict__ gw) {
    int warp = threadIdx.x >> 5;
    int lane = threadIdx.x & 31;
    int t = blockIdx.x * (blockDim.x >> 5) + warp;
    if (t >= NTOK) return;

    float p[NE];
#pragma unroll
    for (int e = 0; e < NE; e++) p[e] = 0.0f;

    const float* xr = x + (size_t)t * HDIM;
    for (int h = lane; h < HDIM; h += 32) {
        float xv = xr[h];
#pragma unroll
        for (int e = 0; e < NE; e++) p[e] += xv * gw[e * HDIM + h];
    }
#pragma unroll
    for (int e = 0; e < NE; e++) {
#pragma unroll
        for (int s = 16; s > 0; s >>= 1) p[e] += __shfl_xor_sync(0xffffffffu, p[e], s);
    }

    if (lane == 0) {
        float m = p[0];
#pragma unroll
        for (int e = 1; e < NE; e++) m = fmaxf(m, p[e]);
        float Z = 0.0f;
        float pr[NE];
#pragma unroll
        for (int e = 0; e < NE; e++) { pr[e] = expf(p[e] - m); Z += pr[e]; }
        float invZ = 1.0f / Z;
#pragma unroll
        for (int e = 0; e < NE; e++) pr[e] *= invZ;

        // top-2 (strict >: lowest index wins ties, matching jax top_k)
        int e1 = 0; float v1 = pr[0];
#pragma unroll
        for (int e = 1; e < NE; e++) if (pr[e] > v1) { v1 = pr[e]; e1 = e; }
        int e2 = -1; float v2 = -1.0f;
#pragma unroll
        for (int e = 0; e < NE; e++) if (e != e1 && pr[e] > v2) { v2 = pr[e]; e2 = e; }

        float s  = v1 + v2;
        float r1 = v1 / s, r2 = v2 / s;

        float lse = m + logf(Z);
        g_zsq[t] = lse * lse;
        g_wa[t]  = v1;
        g_wb[t]  = v2;
        g_ma[t]  = (e1 == 0 || e2 == 0) ? 1.0f : 0.0f;
        g_mb[t]  = (e1 == 1 || e2 == 1) ? 1.0f : 0.0f;

        int s1 = atomicAdd(&g_count[e1], 1);
        g_tok[e1 * NTOK + s1] = t; g_wt[e1 * NTOK + s1] = r1;
        int s2 = atomicAdd(&g_count[e2], 1);
        g_tok[e2 * NTOK + s2] = t; g_wt[e2 * NTOK + s2] = r2;
    }
}

// Single block: losses + prefix offsets.
__global__ void finalize_kernel(float* out, int out_size) {
    int tid = threadIdx.x;
    float s[5] = {0, 0, 0, 0, 0};
    for (int i = tid; i < NTOK; i += 256) {
        s[0] += g_zsq[i]; s[1] += g_wa[i]; s[2] += g_wb[i];
        s[3] += g_ma[i];  s[4] += g_mb[i];
    }
    __shared__ float red[256];
    __shared__ float tot[5];
#pragma unroll
    for (int q = 0; q < 5; q++) {
        red[tid] = s[q];
        __syncthreads();
        for (int st = 128; st > 0; st >>= 1) {
            if (tid < st) red[tid] += red[tid + st];
            __syncthreads();
        }
        if (tid == 0) tot[q] = red[0];
        __syncthreads();
    }
    if (tid == 0) {
        const float invT = 1.0f / (float)NTOK;
        float zl  = tot[0] * invT;
        float aux = 2.0f * ((tot[3] * invT) * (tot[1] * invT) +
                            (tot[4] * invT) * (tot[2] * invT));
        long long base = (long long)NTOK * HDIM;
        if ((long long)out_size > base)     out[base]     = zl;
        if ((long long)out_size > base + 1) out[base + 1] = aux;
        int o = 0;
        for (int e = 0; e < NE; e++) { g_off[e] = o; o += g_count[e]; }
    }
}

// ---------------- grouped GEMMs ----------------
// Tile: BM=128, BN=64, BK=16, 256 threads, 8x4 micro-tile, f32x2 FMA.

__global__ void __launch_bounds__(256)
gemm1_kernel(const float* __restrict__ x, const float* __restrict__ w1,
             const float* __restrict__ b1) {
    int e = blockIdx.z;
    int cnt = g_count[e];
    int m0 = blockIdx.y * 128;
    if (m0 >= cnt) return;
    int n0 = blockIdx.x * 64;

    __shared__ __align__(16) float As[16][132];
    __shared__ __align__(16) float Bs[16][64];
    __shared__ int toks[128];

    int tid = threadIdx.x;
    for (int i = tid; i < 128; i += 256) {
        int r = m0 + i; if (r > cnt - 1) r = cnt - 1;
        toks[i] = g_tok[e * NTOK + r];
    }
    __syncthreads();

    const float* Bp = w1 + (size_t)e * HDIM * FDIM + n0;
    int ar = tid >> 2, ac = (tid & 3) << 2;
    int bk = tid >> 4, bc = (tid & 15) << 2;

    const float* Arow0 = x + (size_t)toks[ar] * HDIM + ac;
    const float* Arow1 = x + (size_t)toks[ar + 64] * HDIM + ac;

    float4 a0 = *(const float4*)(Arow0);
    float4 a1 = *(const float4*)(Arow1);
    float4 bv = *(const float4*)(Bp + (size_t)bk * FDIM + bc);

    u64 c2[4][4];
#pragma unroll
    for (int j = 0; j < 4; j++)
#pragma unroll
        for (int n = 0; n < 4; n++) c2[j][n] = 0ull;

    int tx = tid & 15, ty = tid >> 4;
    const int NKT = HDIM / 16;

    for (int kt = 0; kt < NKT; ++kt) {
        As[ac + 0][ar] = a0.x; As[ac + 1][ar] = a0.y;
        As[ac + 2][ar] = a0.z; As[ac + 3][ar] = a0.w;
        As[ac + 0][ar + 64] = a1.x; As[ac + 1][ar + 64] = a1.y;
        As[ac + 2][ar + 64] = a1.z; As[ac + 3][ar + 64] = a1.w;
        *(float4*)&Bs[bk][bc] = bv;
        __syncthreads();

        if (kt + 1 < NKT) {
            int k0 = (kt + 1) * 16;
            a0 = *(const float4*)(Arow0 + k0);
            a1 = *(const float4*)(Arow1 + k0);
            bv = *(const float4*)(Bp + (size_t)(k0 + bk) * FDIM + bc);
        }

#pragma unroll
        for (int kk = 0; kk < 16; kk++) {
            const u64* ap = (const u64*)&As[kk][ty * 8];
            u64 a2_0 = ap[0], a2_1 = ap[1], a2_2 = ap[2], a2_3 = ap[3];
            float4 b4 = *(const float4*)&Bs[kk][tx * 4];
            u64 bb0 = pk2(b4.x, b4.x), bb1 = pk2(b4.y, b4.y);
            u64 bb2 = pk2(b4.z, b4.z), bb3 = pk2(b4.w, b4.w);
            fma2(c2[0][0], a2_0, bb0); fma2(c2[0][1], a2_0, bb1);
            fma2(c2[0][2], a2_0, bb2); fma2(c2[0][3], a2_0, bb3);
            fma2(c2[1][0], a2_1, bb0); fma2(c2[1][1], a2_1, bb1);
            fma2(c2[1][2], a2_1, bb2); fma2(c2[1][3], a2_1, bb3);
            fma2(c2[2][0], a2_2, bb0); fma2(c2[2][1], a2_2, bb1);
            fma2(c2[2][2], a2_2, bb2); fma2(c2[2][3], a2_2, bb3);
            fma2(c2[3][0], a2_3, bb0); fma2(c2[3][1], a2_3, bb1);
            fma2(c2[3][2], a2_3, bb2); fma2(c2[3][3], a2_3, bb3);
        }
        __syncthreads();
    }

    int off = g_off[e];
    const float* bbp = b1 + e * FDIM + n0 + tx * 4;
    float bias0 = bbp[0], bias1 = bbp[1], bias2 = bbp[2], bias3 = bbp[3];

#pragma unroll
    for (int j = 0; j < 4; j++) {
        float2 cc0 = unpk(c2[j][0]), cc1 = unpk(c2[j][1]);
        float2 cc2 = unpk(c2[j][2]), cc3 = unpk(c2[j][3]);
        int mA = m0 + ty * 8 + 2 * j;
        int mB = mA + 1;
        if (mA < cnt) {
            float4 v;
            v.x = silu_f(cc0.x + bias0); v.y = silu_f(cc1.x + bias1);
            v.z = silu_f(cc2.x + bias2); v.w = silu_f(cc3.x + bias3);
            *(float4*)&g_h1[(size_t)(off + mA) * FDIM + n0 + tx * 4] = v;
        }
        if (mB < cnt) {
            float4 v;
            v.x = silu_f(cc0.y + bias0); v.y = silu_f(cc1.y + bias1);
            v.z = silu_f(cc2.y + bias2); v.w = silu_f(cc3.y + bias3);
            *(float4*)&g_h1[(size_t)(off + mB) * FDIM + n0 + tx * 4] = v;
        }
    }
}

__global__ void __launch_bounds__(256)
gemm2_kernel(const float* __restrict__ w2, const float* __restrict__ b2,
             float* __restrict__ out) {
    int e = blockIdx.z;
    int cnt = g_count[e];
    int m0 = blockIdx.y * 128;
    if (m0 >= cnt) return;
    int n0 = blockIdx.x * 64;
    int off = g_off[e];

    __shared__ __align__(16) float As[16][132];
    __shared__ __align__(16) float Bs[16][64];

    int tid = threadIdx.x;
    int ar = tid >> 2, ac = (tid & 3) << 2;
    int bk = tid >> 4, bc = (tid & 15) << 2;

    int r0 = min(m0 + ar, cnt - 1);
    int r1 = min(m0 + ar + 64, cnt - 1);
    const float* Arow0 = g_h1 + (size_t)(off + r0) * FDIM + ac;
    const float* Arow1 = g_h1 + (size_t)(off + r1) * FDIM + ac;
    const float* Bp = w2 + (size_t)e * FDIM * HDIM + n0;

    float4 a0 = *(const float4*)(Arow0);
    float4 a1 = *(const float4*)(Arow1);
    float4 bv = *(const float4*)(Bp + (size_t)bk * HDIM + bc);

    u64 c2[4][4];
#pragma unroll
    for (int j = 0; j < 4; j++)
#pragma unroll
        for (int n = 0; n < 4; n++) c2[j][n] = 0ull;

    int tx = tid & 15, ty = tid >> 4;
    const int NKT = FDIM / 16;

    for (int kt = 0; kt < NKT; ++kt) {
        As[ac + 0][ar] = a0.x; As[ac + 1][ar] = a0.y;
        As[ac + 2][ar] = a0.z; As[ac + 3][ar] = a0.w;
        As[ac + 0][ar + 64] = a1.x; As[ac + 1][ar + 64] = a1.y;
        As[ac + 2][ar + 64] = a1.z; As[ac + 3][ar + 64] = a1.w;
        *(float4*)&Bs[bk][bc] = bv;
        __syncthreads();

        if (kt + 1 < NKT) {
            int k0 = (kt + 1) * 16;
            a0 = *(const float4*)(Arow0 + k0);
            a1 = *(const float4*)(Arow1 + k0);
            bv = *(const float4*)(Bp + (size_t)(k0 + bk) * HDIM + bc);
        }

#pragma unroll
        for (int kk = 0; kk < 16; kk++) {
            const u64* ap = (const u64*)&As[kk][ty * 8];
            u64 a2_0 = ap[0], a2_1 = ap[1], a2_2 = ap[2], a2_3 = ap[3];
            float4 b4 = *(const float4*)&Bs[kk][tx * 4];
            u64 bb0 = pk2(b4.x, b4.x), bb1 = pk2(b4.y, b4.y);
            u64 bb2 = pk2(b4.z, b4.z), bb3 = pk2(b4.w, b4.w);
            fma2(c2[0][0], a2_0, bb0); fma2(c2[0][1], a2_0, bb1);
            fma2(c2[0][2], a2_0, bb2); fma2(c2[0][3], a2_0, bb3);
            fma2(c2[1][0], a2_1, bb0); fma2(c2[1][1], a2_1, bb1);
            fma2(c2[1][2], a2_1, bb2); fma2(c2[1][3], a2_1, bb3);
            fma2(c2[2][0], a2_2, bb0); fma2(c2[2][1], a2_2, bb1);
            fma2(c2[2][2], a2_2, bb2); fma2(c2[2][3], a2_2, bb3);
            fma2(c2[3][0], a2_3, bb0); fma2(c2[3][1], a2_3, bb1);
            fma2(c2[3][2], a2_3, bb2); fma2(c2[3][3], a2_3, bb3);
        }
        __syncthreads();
    }

    const float* bbp = b2 + e * HDIM + n0 + tx * 4;
    float bias0 = bbp[0], bias1 = bbp[1], bias2 = bbp[2], bias3 = bbp[3];

#pragma unroll
    for (int j = 0; j < 4; j++) {
        float2 cc0 = unpk(c2[j][0]), cc1 = unpk(c2[j][1]);
        float2 cc2 = unpk(c2[j][2]), cc3 = unpk(c2[j][3]);
        int mA = m0 + ty * 8 + 2 * j;
        int mB = mA + 1;
        int colb = n0 + tx * 4;
        if (mA < cnt) {
            int tok = g_tok[e * NTOK + mA];
            float wt = g_wt[e * NTOK + mA];
            float* op = out + (size_t)tok * HDIM + colb;
            atomicAdd(op + 0, wt * (cc0.x + bias0));
            atomicAdd(op + 1, wt * (cc1.x + bias1));
            atomicAdd(op + 2, wt * (cc2.x + bias2));
            atomicAdd(op + 3, wt * (cc3.x + bias3));
        }
        if (mB < cnt) {
            int tok = g_tok[e * NTOK + mB];
            float wt = g_wt[e * NTOK + mB];
            float* op = out + (size_t)tok * HDIM + colb;
            atomicAdd(op + 0, wt * (cc0.y + bias0));
            atomicAdd(op + 1, wt * (cc1.y + bias1));
            atomicAdd(op + 2, wt * (cc2.y + bias2));
            atomicAdd(op + 3, wt * (cc3.y + bias3));
        }
    }
}

// ---------------- launch ----------------
extern "C" void kernel_launch(void* const* d_in, const int* in_sizes, int n_in,
                              void* d_out, int out_size) {
    const float* x  = (const float*)d_in[0];
    const float* gw = (const float*)d_in[1];
    const float* w1 = (const float*)d_in[2];
    const float* b1 = (const float*)d_in[3];
    const float* w2 = (const float*)d_in[4];
    const float* b2 = (const float*)d_in[5];
    float* out = (float*)d_out;

    zero_kernel<<<2048, 256>>>(out, out_size);
    reset_kernel<<<1, 32>>>();
    router_kernel<<<NTOK / 8, 256>>>(x, gw);
    finalize_kernel<<<1, 256>>>(out, out_size);
    gemm1_kernel<<<dim3(FDIM / 64, NTOK / 128, NE), 256>>>(x, w1, b1);
    gemm2_kernel<<<dim3(HDIM / 64, NTOK / 128, NE), 256>>>(w2, b2, out);
}

// round 11
// speedup vs baseline: 2.8203x; 2.8188x over previous
#include <cuda_runtime.h>
#include <math.h>
#include <stdint.h>

#define NTOK 4096
#define HDIM 1024
#define FDIM 4096
#define NE   8

#define BM 128
#define BN 128
#define BK 32
#define A_STRIDE 36      // floats, (BK+4): bank-conflict-free fragment reads
#define B_STRIDE 136     // floats, (BN+8)
#define A_FLOATS (BM * A_STRIDE)             // 4608
#define B_FLOATS (BK * B_STRIDE)             // 4352
#define STAGE_FLOATS (A_FLOATS + B_FLOATS)   // 8960
#define DYN_SMEM (2 * STAGE_FLOATS * 4)      // 71680 bytes

// ---------------- device scratch ----------------
__device__ int   g_count[NE];
__device__ int   g_off[NE];
__device__ int   g_tok[NE * NTOK];
__device__ float g_wt[NE * NTOK];
__device__ float g_zsq[NTOK];
__device__ float g_wa[NTOK];
__device__ float g_wb[NTOK];
__device__ float g_ma[NTOK];
__device__ float g_mb[NTOK];
__device__ __align__(16) float g_h1[(size_t)2 * NTOK * FDIM];      // 128 MiB (tf32-rounded)
__device__ __align__(16) float g_xc[(size_t)NTOK * HDIM];          // x, tf32-rounded
__device__ __align__(16) float g_w1c[(size_t)NE * HDIM * FDIM];    // w1, tf32-rounded
__device__ __align__(16) float g_w2c[(size_t)NE * FDIM * HDIM];    // w2, tf32-rounded

// ---------------- helpers ----------------
__device__ __forceinline__ unsigned su32(const void* p) {
    return (unsigned)__cvta_generic_to_shared(p);
}
__device__ __forceinline__ void cp_async16(unsigned dst, const void* src) {
    asm volatile("cp.async.cg.shared.global [%0], [%1], 16;" :: "r"(dst), "l"(src));
}
__device__ __forceinline__ void cp_commit() {
    asm volatile("cp.async.commit_group;" ::: "memory");
}
template<int N> __device__ __forceinline__ void cp_wait() {
    asm volatile("cp.async.wait_group %0;" :: "n"(N) : "memory");
}
__device__ __forceinline__ float tf32r(float f) {
    float r;
    asm("cvt.rna.tf32.f32 %0, %1;" : "=f"(r) : "f"(f));
    return r;
}
__device__ __forceinline__ void mma8(float* d, const unsigned* a, const unsigned* b) {
    asm volatile(
        "mma.sync.aligned.m16n8k8.row.col.f32.tf32.tf32.f32 "
        "{%0,%1,%2,%3}, {%4,%5,%6,%7}, {%8,%9}, {%0,%1,%2,%3};"
        : "+f"(d[0]), "+f"(d[1]), "+f"(d[2]), "+f"(d[3])
        : "r"(a[0]), "r"(a[1]), "r"(a[2]), "r"(a[3]), "r"(b[0]), "r"(b[1]));
}
__device__ __forceinline__ float silu_f(float v) { return v / (1.0f + expf(-v)); }

// ---------------- small kernels ----------------
__global__ void zero_kernel(float* out, int n) {
    for (int i = blockIdx.x * blockDim.x + threadIdx.x; i < n; i += gridDim.x * blockDim.x)
        out[i] = 0.0f;
}
__global__ void reset_kernel() {
    if (threadIdx.x < NE) g_count[threadIdx.x] = 0;
}
__global__ void cvt_kernel(const float* __restrict__ in, float* __restrict__ out, size_t n) {
    size_t i0 = ((size_t)blockIdx.x * blockDim.x + threadIdx.x) * 4;
    size_t stride = (size_t)gridDim.x * blockDim.x * 4;
    for (size_t i = i0; i < n; i += stride) {
        float4 v = *(const float4*)(in + i);
        v.x = tf32r(v.x); v.y = tf32r(v.y); v.z = tf32r(v.z); v.w = tf32r(v.w);
        *(float4*)(out + i) = v;
    }
}

// router: one warp per token (unchanged from passing R8 kernel)
__global__ void router_kernel(const float* __restrict__ x, const float* __restrict__ gw) {
    int warp = threadIdx.x >> 5;
    int lane = threadIdx.x & 31;
    int t = blockIdx.x * (blockDim.x >> 5) + warp;
    if (t >= NTOK) return;

    float p[NE];
#pragma unroll
    for (int e = 0; e < NE; e++) p[e] = 0.0f;
    const float* xr = x + (size_t)t * HDIM;
    for (int h = lane; h < HDIM; h += 32) {
        float xv = xr[h];
#pragma unroll
        for (int e = 0; e < NE; e++) p[e] += xv * gw[e * HDIM + h];
    }
#pragma unroll
    for (int e = 0; e < NE; e++) {
#pragma unroll
        for (int s = 16; s > 0; s >>= 1) p[e] += __shfl_xor_sync(0xffffffffu, p[e], s);
    }
    if (lane == 0) {
        float m = p[0];
#pragma unroll
        for (int e = 1; e < NE; e++) m = fmaxf(m, p[e]);
        float Z = 0.0f; float pr[NE];
#pragma unroll
        for (int e = 0; e < NE; e++) { pr[e] = expf(p[e] - m); Z += pr[e]; }
        float invZ = 1.0f / Z;
#pragma unroll
        for (int e = 0; e < NE; e++) pr[e] *= invZ;
        int e1 = 0; float v1 = pr[0];
#pragma unroll
        for (int e = 1; e < NE; e++) if (pr[e] > v1) { v1 = pr[e]; e1 = e; }
        int e2 = -1; float v2 = -1.0f;
#pragma unroll
        for (int e = 0; e < NE; e++) if (e != e1 && pr[e] > v2) { v2 = pr[e]; e2 = e; }
        float s = v1 + v2;
        float lse = m + logf(Z);
        g_zsq[t] = lse * lse;
        g_wa[t] = v1; g_wb[t] = v2;
        g_ma[t] = (e1 == 0 || e2 == 0) ? 1.0f : 0.0f;
        g_mb[t] = (e1 == 1 || e2 == 1) ? 1.0f : 0.0f;
        int s1 = atomicAdd(&g_count[e1], 1);
        g_tok[e1 * NTOK + s1] = t; g_wt[e1 * NTOK + s1] = v1 / s;
        int s2 = atomicAdd(&g_count[e2], 1);
        g_tok[e2 * NTOK + s2] = t; g_wt[e2 * NTOK + s2] = v2 / s;
    }
}

__global__ void finalize_kernel(float* out, int out_size) {
    int tid = threadIdx.x;
    float s[5] = {0, 0, 0, 0, 0};
    for (int i = tid; i < NTOK; i += 256) {
        s[0] += g_zsq[i]; s[1] += g_wa[i]; s[2] += g_wb[i];
        s[3] += g_ma[i];  s[4] += g_mb[i];
    }
    __shared__ float red[256];
    __shared__ float tot[5];
#pragma unroll
    for (int q = 0; q < 5; q++) {
        red[tid] = s[q];
        __syncthreads();
        for (int st = 128; st > 0; st >>= 1) {
            if (tid < st) red[tid] += red[tid + st];
            __syncthreads();
        }
        if (tid == 0) tot[q] = red[0];
        __syncthreads();
    }
    if (tid == 0) {
        const float invT = 1.0f / (float)NTOK;
        float zl  = tot[0] * invT;
        float aux = 2.0f * ((tot[3] * invT) * (tot[1] * invT) +
                            (tot[4] * invT) * (tot[2] * invT));
        long long base = (long long)NTOK * HDIM;
        if ((long long)out_size > base)     out[base]     = zl;
        if ((long long)out_size > base + 1) out[base + 1] = aux;
        int o = 0;
        for (int e = 0; e < NE; e++) { g_off[e] = o; o += g_count[e]; }
    }
}

// =====================================================================
// mma.sync tf32 grouped GEMMs. Block 128x128xK, BK=32, 8 warps (2x4),
// warp tile 64x32, 2-stage cp.async double buffer.
// SMEM: As[BM][36] (k minor), Bs[BK][136] (n minor) — padded strides give
// conflict-free fragment reads.
// =====================================================================

// GEMM1: h1[off+m][n] = tf32(silu( sum_k xc[tok[m]][k] * w1c[e][k][n] + b1[e][n] ))
__global__ void __launch_bounds__(256, 2)
gemm1_kernel(const float* __restrict__ b1) {
    int e = blockIdx.z;
    int cnt = g_count[e];
    int m0 = blockIdx.y * BM;
    if (m0 >= cnt) return;
    int n0 = blockIdx.x * BN;
    int off = g_off[e];

    extern __shared__ float smf[];
    __shared__ int toks[BM];

    int tid = threadIdx.x;
    int wid = tid >> 5, lane = tid & 31;

    if (tid < BM) {
        int r = m0 + tid; if (r > cnt - 1) r = cnt - 1;
        toks[tid] = g_tok[e * NTOK + r];
    }
    __syncthreads();

    // per-thread cp.async slots
    unsigned adst[4], bdst[4];
    const char* asrc[4];
    const char* bsrc[4];
    unsigned sbase = su32(smf);
#pragma unroll
    for (int j = 0; j < 4; j++) {
        int idx = tid + 256 * j;
        int row = idx >> 3, ch = idx & 7;               // A: 128 rows x 8 chunks
        adst[j] = sbase + (row * A_STRIDE + ch * 4) * 4;
        asrc[j] = (const char*)(g_xc + (size_t)toks[row] * HDIM + ch * 4);
        int k = idx >> 5, c = idx & 31;                 // B: 32 k-rows x 32 chunks
        bdst[j] = sbase + (A_FLOATS + k * B_STRIDE + c * 4) * 4;
        bsrc[j] = (const char*)(g_w1c + (size_t)e * HDIM * FDIM + (size_t)k * FDIM + n0 + c * 4);
    }
    const size_t aadv = (size_t)BK * 4;            // bytes per kt on A rows
    const size_t badv = (size_t)BK * FDIM * 4;     // bytes per kt on B

    float acc[4][4][4];
#pragma unroll
    for (int i = 0; i < 4; i++)
#pragma unroll
        for (int j = 0; j < 4; j++)
#pragma unroll
            for (int q = 0; q < 4; q++) acc[i][j][q] = 0.0f;

    const int NKT = HDIM / BK;  // 32
    // prologue
#pragma unroll
    for (int s = 0; s < 2; s++) {
        unsigned so = s * STAGE_FLOATS * 4;
#pragma unroll
        for (int j = 0; j < 4; j++) {
            cp_async16(adst[j] + so, asrc[j] + (size_t)s * aadv);
            cp_async16(bdst[j] + so, bsrc[j] + (size_t)s * badv);
        }
        cp_commit();
    }

    int wm = wid >> 2, wn = wid & 3;
    int r = lane >> 2, c = lane & 3;

    for (int kt = 0; kt < NKT; kt++) {
        int s = kt & 1;
        if (kt == NKT - 1) cp_wait<0>(); else cp_wait<1>();
        __syncthreads();

        const float* As = smf + s * STAGE_FLOATS;
        const float* Bs = As + A_FLOATS;
#pragma unroll
        for (int ks = 0; ks < 4; ks++) {
            unsigned af[4][4], bf[4][2];
            int kc = ks * 8 + c;
#pragma unroll
            for (int i = 0; i < 4; i++) {
                int row = wm * 64 + i * 16 + r;
                af[i][0] = __float_as_uint(As[row * A_STRIDE + kc]);
                af[i][1] = __float_as_uint(As[(row + 8) * A_STRIDE + kc]);
                af[i][2] = __float_as_uint(As[row * A_STRIDE + kc + 4]);
                af[i][3] = __float_as_uint(As[(row + 8) * A_STRIDE + kc + 4]);
            }
            int kr = ks * 8 + c;
#pragma unroll
            for (int j = 0; j < 4; j++) {
                int col = wn * 32 + j * 8 + r;
                bf[j][0] = __float_as_uint(Bs[kr * B_STRIDE + col]);
                bf[j][1] = __float_as_uint(Bs[(kr + 4) * B_STRIDE + col]);
            }
#pragma unroll
            for (int i = 0; i < 4; i++)
#pragma unroll
                for (int j = 0; j < 4; j++) mma8(acc[i][j], af[i], bf[j]);
        }
        __syncthreads();

        if (kt + 2 < NKT) {
            unsigned so = s * STAGE_FLOATS * 4;
            size_t ka = (size_t)(kt + 2) * aadv;
            size_t kb = (size_t)(kt + 2) * badv;
#pragma unroll
            for (int j = 0; j < 4; j++) {
                cp_async16(adst[j] + so, asrc[j] + ka);
                cp_async16(bdst[j] + so, bsrc[j] + kb);
            }
            cp_commit();
        }
    }

    // epilogue: bias + silu + tf32-round, direct global stores
#pragma unroll
    for (int i = 0; i < 4; i++) {
        int mrowA = m0 + wm * 64 + i * 16 + r;
        int mrowB = mrowA + 8;
#pragma unroll
        for (int j = 0; j < 4; j++) {
            int ncol = n0 + wn * 32 + j * 8 + c * 2;
            float2 bb = *(const float2*)&b1[(size_t)e * FDIM + ncol];
            if (mrowA < cnt) {
                float2 v;
                v.x = tf32r(silu_f(acc[i][j][0] + bb.x));
                v.y = tf32r(silu_f(acc[i][j][1] + bb.y));
                *(float2*)&g_h1[(size_t)(off + mrowA) * FDIM + ncol] = v;
            }
            if (mrowB < cnt) {
                float2 v;
                v.x = tf32r(silu_f(acc[i][j][2] + bb.x));
                v.y = tf32r(silu_f(acc[i][j][3] + bb.y));
                *(float2*)&g_h1[(size_t)(off + mrowB) * FDIM + ncol] = v;
            }
        }
    }
}

// GEMM2: out[tok[m]][n] += wt[m] * ( sum_k h1[off+m][k] * w2c[e][k][n] + b2[e][n] )
__global__ void __launch_bounds__(256, 2)
gemm2_kernel(const float* __restrict__ b2, float* __restrict__ out) {
    int e = blockIdx.z;
    int cnt = g_count[e];
    int m0 = blockIdx.y * BM;
    if (m0 >= cnt) return;
    int n0 = blockIdx.x * BN;
    int off = g_off[e];

    extern __shared__ float smf[];
    __shared__ int tks[BM];
    __shared__ float wts[BM];

    int tid = threadIdx.x;
    int wid = tid >> 5, lane = tid & 31;

    if (tid < BM) {
        int r = m0 + tid; if (r > cnt - 1) r = cnt - 1;
        tks[tid] = g_tok[e * NTOK + r];
        wts[tid] = g_wt[e * NTOK + r];
    }
    __syncthreads();

    unsigned adst[4], bdst[4];
    const char* asrc[4];
    const char* bsrc[4];
    unsigned sbase = su32(smf);
#pragma unroll
    for (int j = 0; j < 4; j++) {
        int idx = tid + 256 * j;
        int row = idx >> 3, ch = idx & 7;
        int rr = m0 + row; if (rr > cnt - 1) rr = cnt - 1;
        adst[j] = sbase + (row * A_STRIDE + ch * 4) * 4;
        asrc[j] = (const char*)(g_h1 + (size_t)(off + rr) * FDIM + ch * 4);
        int k = idx >> 5, c = idx & 31;
        bdst[j] = sbase + (A_FLOATS + k * B_STRIDE + c * 4) * 4;
        bsrc[j] = (const char*)(g_w2c + (size_t)e * FDIM * HDIM + (size_t)k * HDIM + n0 + c * 4);
    }
    const size_t aadv = (size_t)BK * 4;
    const size_t badv = (size_t)BK * HDIM * 4;

    float acc[4][4][4];
#pragma unroll
    for (int i = 0; i < 4; i++)
#pragma unroll
        for (int j = 0; j < 4; j++)
#pragma unroll
            for (int q = 0; q < 4; q++) acc[i][j][q] = 0.0f;

    const int NKT = FDIM / BK;  // 128
#pragma unroll
    for (int s = 0; s < 2; s++) {
        unsigned so = s * STAGE_FLOATS * 4;
#pragma unroll
        for (int j = 0; j < 4; j++) {
            cp_async16(adst[j] + so, asrc[j] + (size_t)s * aadv);
            cp_async16(bdst[j] + so, bsrc[j] + (size_t)s * badv);
        }
        cp_commit();
    }

    int wm = wid >> 2, wn = wid & 3;
    int r = lane >> 2, c = lane & 3;

    for (int kt = 0; kt < NKT; kt++) {
        int s = kt & 1;
        if (kt == NKT - 1) cp_wait<0>(); else cp_wait<1>();
        __syncthreads();

        const float* As = smf + s * STAGE_FLOATS;
        const float* Bs = As + A_FLOATS;
#pragma unroll
        for (int ks = 0; ks < 4; ks++) {
            unsigned af[4][4], bf[4][2];
            int kc = ks * 8 + c;
#pragma unroll
            for (int i = 0; i < 4; i++) {
                int row = wm * 64 + i * 16 + r;
                af[i][0] = __float_as_uint(As[row * A_STRIDE + kc]);
                af[i][1] = __float_as_uint(As[(row + 8) * A_STRIDE + kc]);
                af[i][2] = __float_as_uint(As[row * A_STRIDE + kc + 4]);
                af[i][3] = __float_as_uint(As[(row + 8) * A_STRIDE + kc + 4]);
            }
            int kr = ks * 8 + c;
#pragma unroll
            for (int j = 0; j < 4; j++) {
                int col = wn * 32 + j * 8 + r;
                bf[j][0] = __float_as_uint(Bs[kr * B_STRIDE + col]);
                bf[j][1] = __float_as_uint(Bs[(kr + 4) * B_STRIDE + col]);
            }
#pragma unroll
            for (int i = 0; i < 4; i++)
#pragma unroll
                for (int j = 0; j < 4; j++) mma8(acc[i][j], af[i], bf[j]);
        }
        __syncthreads();

        if (kt + 2 < NKT) {
            unsigned so = s * STAGE_FLOATS * 4;
            size_t ka = (size_t)(kt + 2) * aadv;
            size_t kb = (size_t)(kt + 2) * badv;
#pragma unroll
            for (int j = 0; j < 4; j++) {
                cp_async16(adst[j] + so, asrc[j] + ka);
                cp_async16(bdst[j] + so, bsrc[j] + kb);
            }
            cp_commit();
        }
    }

#pragma unroll
    for (int i = 0; i < 4; i++) {
        int lrowA = wm * 64 + i * 16 + r;
        int lrowB = lrowA + 8;
        int mrowA = m0 + lrowA, mrowB = m0 + lrowB;
#pragma unroll
        for (int j = 0; j < 4; j++) {
            int ncol = n0 + wn * 32 + j * 8 + c * 2;
            float2 bb = *(const float2*)&b2[(size_t)e * HDIM + ncol];
            if (mrowA < cnt) {
                float w = wts[lrowA];
                float* op = out + (size_t)tks[lrowA] * HDIM + ncol;
                atomicAdd(op + 0, w * (acc[i][j][0] + bb.x));
                atomicAdd(op + 1, w * (acc[i][j][1] + bb.y));
            }
            if (mrowB < cnt) {
                float w = wts[lrowB];
                float* op = out + (size_t)tks[lrowB] * HDIM + ncol;
                atomicAdd(op + 0, w * (acc[i][j][2] + bb.x));
                atomicAdd(op + 1, w * (acc[i][j][3] + bb.y));
            }
        }
    }
}

// ---------------- launch ----------------
extern "C" void kernel_launch(void* const* d_in, const int* in_sizes, int n_in,
                              void* d_out, int out_size) {
    const float* x  = (const float*)d_in[0];
    const float* gw = (const float*)d_in[1];
    const float* w1 = (const float*)d_in[2];
    const float* b1 = (const float*)d_in[3];
    const float* w2 = (const float*)d_in[4];
    const float* b2 = (const float*)d_in[5];
    float* out = (float*)d_out;

    cudaFuncSetAttribute(gemm1_kernel, cudaFuncAttributeMaxDynamicSharedMemorySize, DYN_SMEM);
    cudaFuncSetAttribute(gemm2_kernel, cudaFuncAttributeMaxDynamicSharedMemorySize, DYN_SMEM);

    float* xc;  cudaGetSymbolAddress((void**)&xc,  g_xc);
    float* w1c; cudaGetSymbolAddress((void**)&w1c, g_w1c);
    float* w2c; cudaGetSymbolAddress((void**)&w2c, g_w2c);

    zero_kernel<<<2048, 256>>>(out, out_size);
    reset_kernel<<<1, 32>>>();
    cvt_kernel<<<2048, 256>>>(x,  xc,  (size_t)NTOK * HDIM);
    cvt_kernel<<<4096, 256>>>(w1, w1c, (size_t)NE * HDIM * FDIM);
    cvt_kernel<<<4096, 256>>>(w2, w2c, (size_t)NE * FDIM * HDIM);
    router_kernel<<<NTOK / 8, 256>>>(x, gw);
    finalize_kernel<<<1, 256>>>(out, out_size);
    gemm1_kernel<<<dim3(FDIM / BN, NTOK / BM, NE), 256, DYN_SMEM>>>(b1);
    gemm2_kernel<<<dim3(HDIM / BN, NTOK / BM, NE), 256, DYN_SMEM>>>(b2, out);
}

// round 12
// speedup vs baseline: 2.8810x; 1.0215x over previous
#include <cuda_runtime.h>
#include <math.h>
#include <stdint.h>

#define NTOK 4096
#define HDIM 1024
#define FDIM 4096
#define NE   8

#define BM 128
#define BN 128
#define BK 32
#define NSTAGE 3
#define A_STRIDE 36      // floats (BK+4): conflict-free fragment reads
#define B_STRIDE 136     // floats (BN+8)
#define A_FLOATS (BM * A_STRIDE)             // 4608
#define B_FLOATS (BK * B_STRIDE)             // 4352
#define STAGE_FLOATS (A_FLOATS + B_FLOATS)   // 8960
#define DYN_SMEM (NSTAGE * STAGE_FLOATS * 4) // 107520 bytes

// ---------------- device scratch ----------------
__device__ int   g_count[NE];
__device__ int   g_off[NE];
__device__ int   g_tok[NE * NTOK];
__device__ float g_wt[NE * NTOK];
__device__ float g_zsq[NTOK];
__device__ float g_wa[NTOK];
__device__ float g_wb[NTOK];
__device__ float g_ma[NTOK];
__device__ float g_mb[NTOK];
__device__ __align__(16) float g_h1[(size_t)2 * NTOK * FDIM];      // 128 MiB (tf32-rounded)
__device__ __align__(16) float g_xc[(size_t)NTOK * HDIM];          // x, tf32-rounded
__device__ __align__(16) float g_w1c[(size_t)NE * HDIM * FDIM];    // w1, tf32-rounded
__device__ __align__(16) float g_w2c[(size_t)NE * FDIM * HDIM];    // w2, tf32-rounded

// ---------------- helpers ----------------
__device__ __forceinline__ unsigned su32(const void* p) {
    return (unsigned)__cvta_generic_to_shared(p);
}
__device__ __forceinline__ void cp_async16(unsigned dst, const void* src) {
    asm volatile("cp.async.cg.shared.global [%0], [%1], 16;" :: "r"(dst), "l"(src));
}
__device__ __forceinline__ void cp_commit() {
    asm volatile("cp.async.commit_group;" ::: "memory");
}
template<int N> __device__ __forceinline__ void cp_wait() {
    asm volatile("cp.async.wait_group %0;" :: "n"(N) : "memory");
}
__device__ __forceinline__ float tf32r(float f) {
    float r;
    asm("cvt.rna.tf32.f32 %0, %1;" : "=f"(r) : "f"(f));
    return r;
}
__device__ __forceinline__ void mma8(float* d, const unsigned* a, const unsigned* b) {
    asm volatile(
        "mma.sync.aligned.m16n8k8.row.col.f32.tf32.tf32.f32 "
        "{%0,%1,%2,%3}, {%4,%5,%6,%7}, {%8,%9}, {%0,%1,%2,%3};"
        : "+f"(d[0]), "+f"(d[1]), "+f"(d[2]), "+f"(d[3])
        : "r"(a[0]), "r"(a[1]), "r"(a[2]), "r"(a[3]), "r"(b[0]), "r"(b[1]));
}
__device__ __forceinline__ float silu_f(float v) { return v / (1.0f + expf(-v)); }

// ---------------- small kernels ----------------
__global__ void zero_kernel(float* out, int n) {
    for (int i = blockIdx.x * blockDim.x + threadIdx.x; i < n; i += gridDim.x * blockDim.x)
        out[i] = 0.0f;
}
__global__ void reset_kernel() {
    if (threadIdx.x < NE) g_count[threadIdx.x] = 0;
}
__global__ void cvt_kernel(const float* __restrict__ in, float* __restrict__ out, size_t n) {
    size_t i0 = ((size_t)blockIdx.x * blockDim.x + threadIdx.x) * 8;
    size_t stride = (size_t)gridDim.x * blockDim.x * 8;
    for (size_t i = i0; i < n; i += stride) {
        float4 v = *(const float4*)(in + i);
        float4 u = *(const float4*)(in + i + 4);
        v.x = tf32r(v.x); v.y = tf32r(v.y); v.z = tf32r(v.z); v.w = tf32r(v.w);
        u.x = tf32r(u.x); u.y = tf32r(u.y); u.z = tf32r(u.z); u.w = tf32r(u.w);
        *(float4*)(out + i) = v;
        *(float4*)(out + i + 4) = u;
    }
}

// router: one warp per token
__global__ void router_kernel(const float* __restrict__ x, const float* __restrict__ gw) {
    int warp = threadIdx.x >> 5;
    int lane = threadIdx.x & 31;
    int t = blockIdx.x * (blockDim.x >> 5) + warp;
    if (t >= NTOK) return;

    float p[NE];
#pragma unroll
    for (int e = 0; e < NE; e++) p[e] = 0.0f;
    const float* xr = x + (size_t)t * HDIM;
    for (int h = lane; h < HDIM; h += 32) {
        float xv = xr[h];
#pragma unroll
        for (int e = 0; e < NE; e++) p[e] += xv * gw[e * HDIM + h];
    }
#pragma unroll
    for (int e = 0; e < NE; e++) {
#pragma unroll
        for (int s = 16; s > 0; s >>= 1) p[e] += __shfl_xor_sync(0xffffffffu, p[e], s);
    }
    if (lane == 0) {
        float m = p[0];
#pragma unroll
        for (int e = 1; e < NE; e++) m = fmaxf(m, p[e]);
        float Z = 0.0f; float pr[NE];
#pragma unroll
        for (int e = 0; e < NE; e++) { pr[e] = expf(p[e] - m); Z += pr[e]; }
        float invZ = 1.0f / Z;
#pragma unroll
        for (int e = 0; e < NE; e++) pr[e] *= invZ;
        int e1 = 0; float v1 = pr[0];
#pragma unroll
        for (int e = 1; e < NE; e++) if (pr[e] > v1) { v1 = pr[e]; e1 = e; }
        int e2 = -1; float v2 = -1.0f;
#pragma unroll
        for (int e = 0; e < NE; e++) if (e != e1 && pr[e] > v2) { v2 = pr[e]; e2 = e; }
        float s = v1 + v2;
        float lse = m + logf(Z);
        g_zsq[t] = lse * lse;
        g_wa[t] = v1; g_wb[t] = v2;
        g_ma[t] = (e1 == 0 || e2 == 0) ? 1.0f : 0.0f;
        g_mb[t] = (e1 == 1 || e2 == 1) ? 1.0f : 0.0f;
        int s1 = atomicAdd(&g_count[e1], 1);
        g_tok[e1 * NTOK + s1] = t; g_wt[e1 * NTOK + s1] = v1 / s;
        int s2 = atomicAdd(&g_count[e2], 1);
        g_tok[e2 * NTOK + s2] = t; g_wt[e2 * NTOK + s2] = v2 / s;
    }
}

__global__ void finalize_kernel(float* out, int out_size) {
    int tid = threadIdx.x;
    float s[5] = {0, 0, 0, 0, 0};
    for (int i = tid; i < NTOK; i += 256) {
        s[0] += g_zsq[i]; s[1] += g_wa[i]; s[2] += g_wb[i];
        s[3] += g_ma[i];  s[4] += g_mb[i];
    }
    __shared__ float red[256];
    __shared__ float tot[5];
#pragma unroll
    for (int q = 0; q < 5; q++) {
        red[tid] = s[q];
        __syncthreads();
        for (int st = 128; st > 0; st >>= 1) {
            if (tid < st) red[tid] += red[tid + st];
            __syncthreads();
        }
        if (tid == 0) tot[q] = red[0];
        __syncthreads();
    }
    if (tid == 0) {
        const float invT = 1.0f / (float)NTOK;
        float zl  = tot[0] * invT;
        float aux = 2.0f * ((tot[3] * invT) * (tot[1] * invT) +
                            (tot[4] * invT) * (tot[2] * invT));
        long long base = (long long)NTOK * HDIM;
        if ((long long)out_size > base)     out[base]     = zl;
        if ((long long)out_size > base + 1) out[base + 1] = aux;
        int o = 0;
        for (int e = 0; e < NE; e++) { g_off[e] = o; o += g_count[e]; }
    }
}

// =====================================================================
// mma.sync tf32 grouped GEMMs. Block 128x128xBK32, 4 warps (2x2),
// warp tile 64x64, 3-stage cp.async pipeline, one sync per k-iter.
// =====================================================================

// GEMM1: h1[off+m][n] = tf32(silu( sum_k xc[tok[m]][k] * w1c[e][k][n] + b1[e][n] ))
__global__ void __launch_bounds__(128, 2)
gemm1_kernel(const float* __restrict__ b1) {
    int e = blockIdx.z;
    int cnt = g_count[e];
    int m0 = blockIdx.y * BM;
    if (m0 >= cnt) return;
    int n0 = blockIdx.x * BN;
    int off = g_off[e];

    extern __shared__ float smf[];
    __shared__ int toks[BM];

    int tid = threadIdx.x;
    int wid = tid >> 5, lane = tid & 31;

    if (tid < BM) {
        int r = m0 + tid; if (r > cnt - 1) r = cnt - 1;
        toks[tid] = g_tok[e * NTOK + r];
    }
    __syncthreads();

    // per-thread cp.async slots: 8 A chunks + 8 B chunks per stage
    unsigned adst[8], bdst[8];
    const char* asrc[8];
    const char* bsrc[8];
    unsigned sbase = su32(smf);
#pragma unroll
    for (int j = 0; j < 8; j++) {
        int idx = tid + 128 * j;
        int row = idx >> 3, ch = idx & 7;               // A: 128 rows x 8 chunks of 16B
        adst[j] = sbase + (row * A_STRIDE + ch * 4) * 4;
        asrc[j] = (const char*)(g_xc + (size_t)toks[row] * HDIM + ch * 4);
        int k = idx >> 5, c = idx & 31;                 // B: 32 k-rows x 32 chunks of 16B
        bdst[j] = sbase + (A_FLOATS + k * B_STRIDE + c * 4) * 4;
        bsrc[j] = (const char*)(g_w1c + (size_t)e * HDIM * FDIM + (size_t)k * FDIM + n0 + c * 4);
    }
    const size_t aadv = (size_t)BK * 4;
    const size_t badv = (size_t)BK * FDIM * 4;

    float acc[4][8][4];
#pragma unroll
    for (int i = 0; i < 4; i++)
#pragma unroll
        for (int j = 0; j < 8; j++)
#pragma unroll
            for (int q = 0; q < 4; q++) acc[i][j][q] = 0.0f;

    const int NKT = HDIM / BK;  // 32
#pragma unroll
    for (int s = 0; s < 2; s++) {
        unsigned so = s * STAGE_FLOATS * 4;
#pragma unroll
        for (int j = 0; j < 8; j++) {
            cp_async16(adst[j] + so, asrc[j] + (size_t)s * aadv);
            cp_async16(bdst[j] + so, bsrc[j] + (size_t)s * badv);
        }
        cp_commit();
    }

    int wm = wid >> 1, wn = wid & 1;
    int r = lane >> 2, c = lane & 3;

    for (int kt = 0; kt < NKT; kt++) {
        if (kt == NKT - 1) cp_wait<0>(); else cp_wait<1>();
        __syncthreads();

        if (kt + 2 < NKT) {
            unsigned so = ((kt + 2) % NSTAGE) * STAGE_FLOATS * 4;
            size_t ka = (size_t)(kt + 2) * aadv;
            size_t kb = (size_t)(kt + 2) * badv;
#pragma unroll
            for (int j = 0; j < 8; j++) {
                cp_async16(adst[j] + so, asrc[j] + ka);
                cp_async16(bdst[j] + so, bsrc[j] + kb);
            }
            cp_commit();
        }

        const float* As = smf + (kt % NSTAGE) * STAGE_FLOATS;
        const float* Bs = As + A_FLOATS;
#pragma unroll
        for (int ks = 0; ks < 4; ks++) {
            unsigned af[4][4], bf[8][2];
            int kc = ks * 8 + c;
#pragma unroll
            for (int i = 0; i < 4; i++) {
                int row = wm * 64 + i * 16 + r;
                af[i][0] = __float_as_uint(As[row * A_STRIDE + kc]);
                af[i][1] = __float_as_uint(As[(row + 8) * A_STRIDE + kc]);
                af[i][2] = __float_as_uint(As[row * A_STRIDE + kc + 4]);
                af[i][3] = __float_as_uint(As[(row + 8) * A_STRIDE + kc + 4]);
            }
#pragma unroll
            for (int j = 0; j < 8; j++) {
                int col = wn * 64 + j * 8 + r;
                bf[j][0] = __float_as_uint(Bs[kc * B_STRIDE + col]);
                bf[j][1] = __float_as_uint(Bs[(kc + 4) * B_STRIDE + col]);
            }
#pragma unroll
            for (int i = 0; i < 4; i++)
#pragma unroll
                for (int j = 0; j < 8; j++) mma8(acc[i][j], af[i], bf[j]);
        }
    }

    // epilogue: bias + silu + tf32-round, direct global stores
#pragma unroll
    for (int i = 0; i < 4; i++) {
        int mrowA = m0 + wm * 64 + i * 16 + r;
        int mrowB = mrowA + 8;
#pragma unroll
        for (int j = 0; j < 8; j++) {
            int ncol = n0 + wn * 64 + j * 8 + c * 2;
            float2 bb = *(const float2*)&b1[(size_t)e * FDIM + ncol];
            if (mrowA < cnt) {
                float2 v;
                v.x = tf32r(silu_f(acc[i][j][0] + bb.x));
                v.y = tf32r(silu_f(acc[i][j][1] + bb.y));
                *(float2*)&g_h1[(size_t)(off + mrowA) * FDIM + ncol] = v;
            }
            if (mrowB < cnt) {
                float2 v;
                v.x = tf32r(silu_f(acc[i][j][2] + bb.x));
                v.y = tf32r(silu_f(acc[i][j][3] + bb.y));
                *(float2*)&g_h1[(size_t)(off + mrowB) * FDIM + ncol] = v;
            }
        }
    }
}

// GEMM2: out[tok[m]][n] += wt[m] * ( sum_k h1[off+m][k] * w2c[e][k][n] + b2[e][n] )
__global__ void __launch_bounds__(128, 2)
gemm2_kernel(const float* __restrict__ b2, float* __restrict__ out) {
    int e = blockIdx.z;
    int cnt = g_count[e];
    int m0 = blockIdx.y * BM;
    if (m0 >= cnt) return;
    int n0 = blockIdx.x * BN;
    int off = g_off[e];

    extern __shared__ float smf[];
    __shared__ int tks[BM];
    __shared__ float wts[BM];

    int tid = threadIdx.x;
    int wid = tid >> 5, lane = tid & 31;

    if (tid < BM) {
        int r = m0 + tid; if (r > cnt - 1) r = cnt - 1;
        tks[tid] = g_tok[e * NTOK + r];
        wts[tid] = g_wt[e * NTOK + r];
    }
    __syncthreads();

    unsigned adst[8], bdst[8];
    const char* asrc[8];
    const char* bsrc[8];
    unsigned sbase = su32(smf);
#pragma unroll
    for (int j = 0; j < 8; j++) {
        int idx = tid + 128 * j;
        int row = idx >> 3, ch = idx & 7;
        int rr = m0 + row; if (rr > cnt - 1) rr = cnt - 1;
        adst[j] = sbase + (row * A_STRIDE + ch * 4) * 4;
        asrc[j] = (const char*)(g_h1 + (size_t)(off + rr) * FDIM + ch * 4);
        int k = idx >> 5, c = idx & 31;
        bdst[j] = sbase + (A_FLOATS + k * B_STRIDE + c * 4) * 4;
        bsrc[j] = (const char*)(g_w2c + (size_t)e * FDIM * HDIM + (size_t)k * HDIM + n0 + c * 4);
    }
    const size_t aadv = (size_t)BK * 4;
    const size_t badv = (size_t)BK * HDIM * 4;

    float acc[4][8][4];
#pragma unroll
    for (int i = 0; i < 4; i++)
#pragma unroll
        for (int j = 0; j < 8; j++)
#pragma unroll
            for (int q = 0; q < 4; q++) acc[i][j][q] = 0.0f;

    const int NKT = FDIM / BK;  // 128
#pragma unroll
    for (int s = 0; s < 2; s++) {
        unsigned so = s * STAGE_FLOATS * 4;
#pragma unroll
        for (int j = 0; j < 8; j++) {
            cp_async16(adst[j] + so, asrc[j] + (size_t)s * aadv);
            cp_async16(bdst[j] + so, bsrc[j] + (size_t)s * badv);
        }
        cp_commit();
    }

    int wm = wid >> 1, wn = wid & 1;
    int r = lane >> 2, c = lane & 3;

    for (int kt = 0; kt < NKT; kt++) {
        if (kt == NKT - 1) cp_wait<0>(); else cp_wait<1>();
        __syncthreads();

        if (kt + 2 < NKT) {
            unsigned so = ((kt + 2) % NSTAGE) * STAGE_FLOATS * 4;
            size_t ka = (size_t)(kt + 2) * aadv;
            size_t kb = (size_t)(kt + 2) * badv;
#pragma unroll
            for (int j = 0; j < 8; j++) {
                cp_async16(adst[j] + so, asrc[j] + ka);
                cp_async16(bdst[j] + so, bsrc[j] + kb);
            }
            cp_commit();
        }

        const float* As = smf + (kt % NSTAGE) * STAGE_FLOATS;
        const float* Bs = As + A_FLOATS;
#pragma unroll
        for (int ks = 0; ks < 4; ks++) {
            unsigned af[4][4], bf[8][2];
            int kc = ks * 8 + c;
#pragma unroll
            for (int i = 0; i < 4; i++) {
                int row = wm * 64 + i * 16 + r;
                af[i][0] = __float_as_uint(As[row * A_STRIDE + kc]);
                af[i][1] = __float_as_uint(As[(row + 8) * A_STRIDE + kc]);
                af[i][2] = __float_as_uint(As[row * A_STRIDE + kc + 4]);
                af[i][3] = __float_as_uint(As[(row + 8) * A_STRIDE + kc + 4]);
            }
#pragma unroll
            for (int j = 0; j < 8; j++) {
                int col = wn * 64 + j * 8 + r;
                bf[j][0] = __float_as_uint(Bs[kc * B_STRIDE + col]);
                bf[j][1] = __float_as_uint(Bs[(kc + 4) * B_STRIDE + col]);
            }
#pragma unroll
            for (int i = 0; i < 4; i++)
#pragma unroll
                for (int j = 0; j < 8; j++) mma8(acc[i][j], af[i], bf[j]);
        }
    }

#pragma unroll
    for (int i = 0; i < 4; i++) {
        int lrowA = wm * 64 + i * 16 + r;
        int lrowB = lrowA + 8;
        int mrowA = m0 + lrowA, mrowB = m0 + lrowB;
#pragma unroll
        for (int j = 0; j < 8; j++) {
            int ncol = n0 + wn * 64 + j * 8 + c * 2;
            float2 bb = *(const float2*)&b2[(size_t)e * HDIM + ncol];
            if (mrowA < cnt) {
                float w = wts[lrowA];
                float* op = out + (size_t)tks[lrowA] * HDIM + ncol;
                atomicAdd(op + 0, w * (acc[i][j][0] + bb.x));
                atomicAdd(op + 1, w * (acc[i][j][1] + bb.y));
            }
            if (mrowB < cnt) {
                float w = wts[lrowB];
                float* op = out + (size_t)tks[lrowB] * HDIM + ncol;
                atomicAdd(op + 0, w * (acc[i][j][2] + bb.x));
                atomicAdd(op + 1, w * (acc[i][j][3] + bb.y));
            }
        }
    }
}

// ---------------- launch ----------------
extern "C" void kernel_launch(void* const* d_in, const int* in_sizes, int n_in,
                              void* d_out, int out_size) {
    const float* x  = (const float*)d_in[0];
    const float* gw = (const float*)d_in[1];
    const float* w1 = (const float*)d_in[2];
    const float* b1 = (const float*)d_in[3];
    const float* w2 = (const float*)d_in[4];
    const float* b2 = (const float*)d_in[5];
    float* out = (float*)d_out;

    cudaFuncSetAttribute(gemm1_kernel, cudaFuncAttributeMaxDynamicSharedMemorySize, DYN_SMEM);
    cudaFuncSetAttribute(gemm2_kernel, cudaFuncAttributeMaxDynamicSharedMemorySize, DYN_SMEM);

    float* xc;  cudaGetSymbolAddress((void**)&xc,  g_xc);
    float* w1c; cudaGetSymbolAddress((void**)&w1c, g_w1c);
    float* w2c; cudaGetSymbolAddress((void**)&w2c, g_w2c);

    zero_kernel<<<2048, 256>>>(out, out_size);
    reset_kernel<<<1, 32>>>();
    cvt_kernel<<<1024, 256>>>(x,  xc,  (size_t)NTOK * HDIM);
    cvt_kernel<<<4096, 256>>>(w1, w1c, (size_t)NE * HDIM * FDIM);
    cvt_kernel<<<4096, 256>>>(w2, w2c, (size_t)NE * FDIM * HDIM);
    router_kernel<<<NTOK / 8, 256>>>(x, gw);
    finalize_kernel<<<1, 256>>>(out, out_size);
    gemm1_kernel<<<dim3(FDIM / BN, NTOK / BM, NE), 128, DYN_SMEM>>>(b1);
    gemm2_kernel<<<dim3(HDIM / BN, NTOK / BM, NE), 128, DYN_SMEM>>>(b2, out);
}

// round 13
// speedup vs baseline: 4.1656x; 1.4459x over previous
#include <cuda_runtime.h>
#include <cuda_fp16.h>
#include <math.h>
#include <stdint.h>

#define NTOK 4096
#define HDIM 1024
#define FDIM 4096
#define NE   8

#define BM 128
#define BN 128
#define BK 32
#define NSTAGE 4
#define S2 20                            // row stride in 32-bit words (40 halves)
#define A_WORDS (BM * S2)                // 2560
#define STAGE_WORDS (2 * A_WORDS)        // 5120 (20 KB)
#define DYN_SMEM (NSTAGE * STAGE_WORDS * 4)  // 81920 bytes

// ---------------- device scratch ----------------
__device__ int   g_count[NE];
__device__ int   g_off[NE];
__device__ int   g_tok[NE * NTOK];
__device__ float g_wt[NE * NTOK];
__device__ float g_zsq[NTOK];
__device__ float g_wa[NTOK];
__device__ float g_wb[NTOK];
__device__ float g_ma[NTOK];
__device__ float g_mb[NTOK];
__device__ __align__(16) __half g_h1f[(size_t)2 * NTOK * FDIM];   // 64 MiB
__device__ __align__(16) __half g_xh[(size_t)NTOK * HDIM];        // 8 MiB
__device__ __align__(16) __half g_w1t[(size_t)NE * FDIM * HDIM];  // 64 MiB: [E][F][H]
__device__ __align__(16) __half g_w2t[(size_t)NE * HDIM * FDIM];  // 64 MiB: [E][H][F]

// ---------------- helpers ----------------
__device__ __forceinline__ unsigned su32(const void* p) {
    return (unsigned)__cvta_generic_to_shared(p);
}
__device__ __forceinline__ void cp_async16(unsigned dst, const void* src) {
    asm volatile("cp.async.cg.shared.global [%0], [%1], 16;" :: "r"(dst), "l"(src));
}
__device__ __forceinline__ void cp_commit() {
    asm volatile("cp.async.commit_group;" ::: "memory");
}
template<int N> __device__ __forceinline__ void cp_wait() {
    asm volatile("cp.async.wait_group %0;" :: "n"(N) : "memory");
}
// fp16 HMMA: m16n8k16, f32 accumulate
__device__ __forceinline__ void mma16(float* d, const unsigned* a, const unsigned* b) {
    asm volatile(
        "mma.sync.aligned.m16n8k16.row.col.f32.f16.f16.f32 "
        "{%0,%1,%2,%3}, {%4,%5,%6,%7}, {%8,%9}, {%0,%1,%2,%3};"
        : "+f"(d[0]), "+f"(d[1]), "+f"(d[2]), "+f"(d[3])
        : "r"(a[0]), "r"(a[1]), "r"(a[2]), "r"(a[3]), "r"(b[0]), "r"(b[1]));
}
__device__ __forceinline__ float silu_f(float v) { return v / (1.0f + expf(-v)); }

// ---------------- small kernels ----------------
__global__ void zero_kernel(float* out, int n) {
    for (int i = blockIdx.x * blockDim.x + threadIdx.x; i < n; i += gridDim.x * blockDim.x)
        out[i] = 0.0f;
}
__global__ void reset_kernel() {
    if (threadIdx.x < NE) g_count[threadIdx.x] = 0;
}
// x: fp32 -> fp16 elementwise
__global__ void cvt16_kernel(const float* __restrict__ in, __half* __restrict__ out, size_t n) {
    size_t i0 = ((size_t)blockIdx.x * blockDim.x + threadIdx.x) * 8;
    size_t stride = (size_t)gridDim.x * blockDim.x * 8;
    for (size_t i = i0; i < n; i += stride) {
        float4 v = *(const float4*)(in + i);
        float4 u = *(const float4*)(in + i + 4);
        __half2 h0 = __floats2half2_rn(v.x, v.y);
        __half2 h1 = __floats2half2_rn(v.z, v.w);
        __half2 h2 = __floats2half2_rn(u.x, u.y);
        __half2 h3 = __floats2half2_rn(u.z, u.w);
        uint4 o;
        o.x = *(unsigned*)&h0; o.y = *(unsigned*)&h1;
        o.z = *(unsigned*)&h2; o.w = *(unsigned*)&h3;
        *(uint4*)(out + i) = o;
    }
}
// transpose + convert: in fp32 [E][R][C] -> out fp16 [E][C][R]
__device__ __forceinline__ void transcvt_body(const float* __restrict__ in,
                                              __half* __restrict__ out, int R, int C) {
    __shared__ float tile[32][33];
    int e = blockIdx.z;
    const float* ip = in + (size_t)e * R * C;
    __half* op = out + (size_t)e * R * C;
    int c0 = blockIdx.x * 32, r0 = blockIdx.y * 32;
#pragma unroll
    for (int i = 0; i < 4; i++) {
        int r = r0 + threadIdx.y + i * 8;
        tile[threadIdx.y + i * 8][threadIdx.x] = ip[(size_t)r * C + c0 + threadIdx.x];
    }
    __syncthreads();
#pragma unroll
    for (int i = 0; i < 4; i++) {
        int c = c0 + threadIdx.y + i * 8;
        op[(size_t)c * R + r0 + threadIdx.x] = __float2half_rn(tile[threadIdx.x][threadIdx.y + i * 8]);
    }
}
__global__ void transcvt_w1(const float* __restrict__ w1) { transcvt_body(w1, g_w1t, HDIM, FDIM); }
__global__ void transcvt_w2(const float* __restrict__ w2) { transcvt_body(w2, g_w2t, FDIM, HDIM); }

// router: one warp per token
__global__ void router_kernel(const float* __restrict__ x, const float* __restrict__ gw) {
    int warp = threadIdx.x >> 5;
    int lane = threadIdx.x & 31;
    int t = blockIdx.x * (blockDim.x >> 5) + warp;
    if (t >= NTOK) return;

    float p[NE];
#pragma unroll
    for (int e = 0; e < NE; e++) p[e] = 0.0f;
    const float* xr = x + (size_t)t * HDIM;
    for (int h = lane; h < HDIM; h += 32) {
        float xv = xr[h];
#pragma unroll
        for (int e = 0; e < NE; e++) p[e] += xv * gw[e * HDIM + h];
    }
#pragma unroll
    for (int e = 0; e < NE; e++) {
#pragma unroll
        for (int s = 16; s > 0; s >>= 1) p[e] += __shfl_xor_sync(0xffffffffu, p[e], s);
    }
    if (lane == 0) {
        float m = p[0];
#pragma unroll
        for (int e = 1; e < NE; e++) m = fmaxf(m, p[e]);
        float Z = 0.0f; float pr[NE];
#pragma unroll
        for (int e = 0; e < NE; e++) { pr[e] = expf(p[e] - m); Z += pr[e]; }
        float invZ = 1.0f / Z;
#pragma unroll
        for (int e = 0; e < NE; e++) pr[e] *= invZ;
        int e1 = 0; float v1 = pr[0];
#pragma unroll
        for (int e = 1; e < NE; e++) if (pr[e] > v1) { v1 = pr[e]; e1 = e; }
        int e2 = -1; float v2 = -1.0f;
#pragma unroll
        for (int e = 0; e < NE; e++) if (e != e1 && pr[e] > v2) { v2 = pr[e]; e2 = e; }
        float s = v1 + v2;
        float lse = m + logf(Z);
        g_zsq[t] = lse * lse;
        g_wa[t] = v1; g_wb[t] = v2;
        g_ma[t] = (e1 == 0 || e2 == 0) ? 1.0f : 0.0f;
        g_mb[t] = (e1 == 1 || e2 == 1) ? 1.0f : 0.0f;
        int s1 = atomicAdd(&g_count[e1], 1);
        g_tok[e1 * NTOK + s1] = t; g_wt[e1 * NTOK + s1] = v1 / s;
        int s2 = atomicAdd(&g_count[e2], 1);
        g_tok[e2 * NTOK + s2] = t; g_wt[e2 * NTOK + s2] = v2 / s;
    }
}

__global__ void finalize_kernel(float* out, int out_size) {
    int tid = threadIdx.x;
    float s[5] = {0, 0, 0, 0, 0};
    for (int i = tid; i < NTOK; i += 256) {
        s[0] += g_zsq[i]; s[1] += g_wa[i]; s[2] += g_wb[i];
        s[3] += g_ma[i];  s[4] += g_mb[i];
    }
    __shared__ float red[256];
    __shared__ float tot[5];
#pragma unroll
    for (int q = 0; q < 5; q++) {
        red[tid] = s[q];
        __syncthreads();
        for (int st = 128; st > 0; st >>= 1) {
            if (tid < st) red[tid] += red[tid + st];
            __syncthreads();
        }
        if (tid == 0) tot[q] = red[0];
        __syncthreads();
    }
    if (tid == 0) {
        const float invT = 1.0f / (float)NTOK;
        float zl  = tot[0] * invT;
        float aux = 2.0f * ((tot[3] * invT) * (tot[1] * invT) +
                            (tot[4] * invT) * (tot[2] * invT));
        long long base = (long long)NTOK * HDIM;
        if ((long long)out_size > base)     out[base]     = zl;
        if ((long long)out_size > base + 1) out[base + 1] = aux;
        int o = 0;
        for (int e = 0; e < NE; e++) { g_off[e] = o; o += g_count[e]; }
    }
}

// =====================================================================
// fp16 mma.sync grouped GEMMs. Block 128x128xBK32, 4 warps (2x2),
// warp tile 64x64, m16n8k16, 4-stage cp.async pipeline.
// SMEM rows (both A[m][k] and B[n][k]): 32 halves + pad, stride S2=20
// words -> conflict-free 32-bit fragment reads ((20r+c) bijective mod 32).
// =====================================================================

// GEMM1: h1f[off+m][n] = fp16(silu( sum_k xh[tok[m]][k] * w1t[e][n][k] + b1[e][n] ))
__global__ void __launch_bounds__(128, 2)
gemm1_kernel(const float* __restrict__ b1) {
    int e = blockIdx.z;
    int cnt = g_count[e];
    int m0 = blockIdx.y * BM;
    if (m0 >= cnt) return;
    int n0 = blockIdx.x * BN;
    int off = g_off[e];

    extern __shared__ unsigned smw[];
    __shared__ int toks[BM];

    int tid = threadIdx.x;
    int wid = tid >> 5, lane = tid & 31;

    if (tid < BM) {
        int r = m0 + tid; if (r > cnt - 1) r = cnt - 1;
        toks[tid] = g_tok[e * NTOK + r];
    }
    __syncthreads();

    // cp.async slots: 4 A chunks + 4 B chunks of 16B per thread per stage
    unsigned adst[4], bdst[4];
    const char* asrc[4];
    const char* bsrc[4];
    unsigned sbase = su32(smw);
#pragma unroll
    for (int j = 0; j < 4; j++) {
        int idx = tid + 128 * j;
        int row = idx >> 2, ch = idx & 3;               // 128 rows x 4 chunks (64B data/row)
        adst[j] = sbase + (row * S2 + ch * 4) * 4;
        asrc[j] = (const char*)(g_xh + (size_t)toks[row] * HDIM) + ch * 16;
        bdst[j] = sbase + (A_WORDS + row * S2 + ch * 4) * 4;
        bsrc[j] = (const char*)(g_w1t + ((size_t)e * FDIM + n0 + row) * HDIM) + ch * 16;
    }
    const size_t kadv = (size_t)BK * 2;   // 64 bytes per kt (both A and B)

    float acc[4][8][4];
#pragma unroll
    for (int i = 0; i < 4; i++)
#pragma unroll
        for (int j = 0; j < 8; j++)
#pragma unroll
            for (int q = 0; q < 4; q++) acc[i][j][q] = 0.0f;

    const int NKT = HDIM / BK;  // 32
#pragma unroll
    for (int s = 0; s < NSTAGE - 1; s++) {
        unsigned so = s * STAGE_WORDS * 4;
#pragma unroll
        for (int j = 0; j < 4; j++) {
            cp_async16(adst[j] + so, asrc[j] + (size_t)s * kadv);
            cp_async16(bdst[j] + so, bsrc[j] + (size_t)s * kadv);
        }
        cp_commit();
    }

    int wm = wid >> 1, wn = wid & 1;
    int r = lane >> 2, c = lane & 3;

    for (int kt = 0; kt < NKT; kt++) {
        if (kt < NKT - 2) cp_wait<2>();
        else if (kt == NKT - 2) cp_wait<1>();
        else cp_wait<0>();
        __syncthreads();

        if (kt + 3 < NKT) {
            unsigned so = ((kt + 3) % NSTAGE) * STAGE_WORDS * 4;
            size_t ka = (size_t)(kt + 3) * kadv;
#pragma unroll
            for (int j = 0; j < 4; j++) {
                cp_async16(adst[j] + so, asrc[j] + ka);
                cp_async16(bdst[j] + so, bsrc[j] + ka);
            }
            cp_commit();
        }

        const unsigned* As = smw + (kt % NSTAGE) * STAGE_WORDS;
        const unsigned* Bs = As + A_WORDS;
#pragma unroll
        for (int ks = 0; ks < 2; ks++) {
            unsigned af[4][4], bf[8][2];
            int kb = ks * 8 + c;
#pragma unroll
            for (int i = 0; i < 4; i++) {
                int row = wm * 64 + i * 16 + r;
                af[i][0] = As[row * S2 + kb];
                af[i][1] = As[(row + 8) * S2 + kb];
                af[i][2] = As[row * S2 + kb + 4];
                af[i][3] = As[(row + 8) * S2 + kb + 4];
            }
#pragma unroll
            for (int j = 0; j < 8; j++) {
                int col = wn * 64 + j * 8 + r;
                bf[j][0] = Bs[col * S2 + kb];
                bf[j][1] = Bs[col * S2 + kb + 4];
            }
#pragma unroll
            for (int i = 0; i < 4; i++)
#pragma unroll
                for (int j = 0; j < 8; j++) mma16(acc[i][j], af[i], bf[j]);
        }
    }

    // epilogue: bias + silu -> fp16, direct global stores
#pragma unroll
    for (int i = 0; i < 4; i++) {
        int mrowA = m0 + wm * 64 + i * 16 + r;
        int mrowB = mrowA + 8;
#pragma unroll
        for (int j = 0; j < 8; j++) {
            int ncol = n0 + wn * 64 + j * 8 + c * 2;
            float2 bb = *(const float2*)&b1[(size_t)e * FDIM + ncol];
            if (mrowA < cnt) {
                __half2 h = __floats2half2_rn(silu_f(acc[i][j][0] + bb.x),
                                              silu_f(acc[i][j][1] + bb.y));
                *(__half2*)&g_h1f[(size_t)(off + mrowA) * FDIM + ncol] = h;
            }
            if (mrowB < cnt) {
                __half2 h = __floats2half2_rn(silu_f(acc[i][j][2] + bb.x),
                                              silu_f(acc[i][j][3] + bb.y));
                *(__half2*)&g_h1f[(size_t)(off + mrowB) * FDIM + ncol] = h;
            }
        }
    }
}

// GEMM2: out[tok[m]][n] += wt[m] * ( sum_k h1f[off+m][k] * w2t[e][n][k] + b2[e][n] )
__global__ void __launch_bounds__(128, 2)
gemm2_kernel(const float* __restrict__ b2, float* __restrict__ out) {
    int e = blockIdx.z;
    int cnt = g_count[e];
    int m0 = blockIdx.y * BM;
    if (m0 >= cnt) return;
    int n0 = blockIdx.x * BN;
    int off = g_off[e];

    extern __shared__ unsigned smw[];
    __shared__ int tks[BM];
    __shared__ float wts[BM];

    int tid = threadIdx.x;
    int wid = tid >> 5, lane = tid & 31;

    if (tid < BM) {
        int r = m0 + tid; if (r > cnt - 1) r = cnt - 1;
        tks[tid] = g_tok[e * NTOK + r];
        wts[tid] = g_wt[e * NTOK + r];
    }
    __syncthreads();

    unsigned adst[4], bdst[4];
    const char* asrc[4];
    const char* bsrc[4];
    unsigned sbase = su32(smw);
#pragma unroll
    for (int j = 0; j < 4; j++) {
        int idx = tid + 128 * j;
        int row = idx >> 2, ch = idx & 3;
        int rr = m0 + row; if (rr > cnt - 1) rr = cnt - 1;
        adst[j] = sbase + (row * S2 + ch * 4) * 4;
        asrc[j] = (const char*)(g_h1f + (size_t)(off + rr) * FDIM) + ch * 16;
        bdst[j] = sbase + (A_WORDS + row * S2 + ch * 4) * 4;
        bsrc[j] = (const char*)(g_w2t + ((size_t)e * HDIM + n0 + row) * FDIM) + ch * 16;
    }
    const size_t kadv = (size_t)BK * 2;

    float acc[4][8][4];
#pragma unroll
    for (int i = 0; i < 4; i++)
#pragma unroll
        for (int j = 0; j < 8; j++)
#pragma unroll
            for (int q = 0; q < 4; q++) acc[i][j][q] = 0.0f;

    const int NKT = FDIM / BK;  // 128
#pragma unroll
    for (int s = 0; s < NSTAGE - 1; s++) {
        unsigned so = s * STAGE_WORDS * 4;
#pragma unroll
        for (int j = 0; j < 4; j++) {
            cp_async16(adst[j] + so, asrc[j] + (size_t)s * kadv);
            cp_async16(bdst[j] + so, bsrc[j] + (size_t)s * kadv);
        }
        cp_commit();
    }

    int wm = wid >> 1, wn = wid & 1;
    int r = lane >> 2, c = lane & 3;

    for (int kt = 0; kt < NKT; kt++) {
        if (kt < NKT - 2) cp_wait<2>();
        else if (kt == NKT - 2) cp_wait<1>();
        else cp_wait<0>();
        __syncthreads();

        if (kt + 3 < NKT) {
            unsigned so = ((kt + 3) % NSTAGE) * STAGE_WORDS * 4;
            size_t ka = (size_t)(kt + 3) * kadv;
#pragma unroll
            for (int j = 0; j < 4; j++) {
                cp_async16(adst[j] + so, asrc[j] + ka);
                cp_async16(bdst[j] + so, bsrc[j] + ka);
            }
            cp_commit();
        }

        const unsigned* As = smw + (kt % NSTAGE) * STAGE_WORDS;
        const unsigned* Bs = As + A_WORDS;
#pragma unroll
        for (int ks = 0; ks < 2; ks++) {
            unsigned af[4][4], bf[8][2];
            int kb = ks * 8 + c;
#pragma unroll
            for (int i = 0; i < 4; i++) {
                int row = wm * 64 + i * 16 + r;
                af[i][0] = As[row * S2 + kb];
                af[i][1] = As[(row + 8) * S2 + kb];
                af[i][2] = As[row * S2 + kb + 4];
                af[i][3] = As[(row + 8) * S2 + kb + 4];
            }
#pragma unroll
            for (int j = 0; j < 8; j++) {
                int col = wn * 64 + j * 8 + r;
                bf[j][0] = Bs[col * S2 + kb];
                bf[j][1] = Bs[col * S2 + kb + 4];
            }
#pragma unroll
            for (int i = 0; i < 4; i++)
#pragma unroll
                for (int j = 0; j < 8; j++) mma16(acc[i][j], af[i], bf[j]);
        }
    }

#pragma unroll
    for (int i = 0; i < 4; i++) {
        int lrowA = wm * 64 + i * 16 + r;
        int lrowB = lrowA + 8;
        int mrowA = m0 + lrowA, mrowB = m0 + lrowB;
#pragma unroll
        for (int j = 0; j < 8; j++) {
            int ncol = n0 + wn * 64 + j * 8 + c * 2;
            float2 bb = *(const float2*)&b2[(size_t)e * HDIM + ncol];
            if (mrowA < cnt) {
                float w = wts[lrowA];
                float* op = out + (size_t)tks[lrowA] * HDIM + ncol;
                atomicAdd(op + 0, w * (acc[i][j][0] + bb.x));
                atomicAdd(op + 1, w * (acc[i][j][1] + bb.y));
            }
            if (mrowB < cnt) {
                float w = wts[lrowB];
                float* op = out + (size_t)tks[lrowB] * HDIM + ncol;
                atomicAdd(op + 0, w * (acc[i][j][2] + bb.x));
                atomicAdd(op + 1, w * (acc[i][j][3] + bb.y));
            }
        }
    }
}

// ---------------- launch ----------------
extern "C" void kernel_launch(void* const* d_in, const int* in_sizes, int n_in,
                              void* d_out, int out_size) {
    const float* x  = (const float*)d_in[0];
    const float* gw = (const float*)d_in[1];
    const float* w1 = (const float*)d_in[2];
    const float* b1 = (const float*)d_in[3];
    const float* w2 = (const float*)d_in[4];
    const float* b2 = (const float*)d_in[5];
    float* out = (float*)d_out;

    cudaFuncSetAttribute(gemm1_kernel, cudaFuncAttributeMaxDynamicSharedMemorySize, DYN_SMEM);
    cudaFuncSetAttribute(gemm2_kernel, cudaFuncAttributeMaxDynamicSharedMemorySize, DYN_SMEM);

    __half* xh; cudaGetSymbolAddress((void**)&xh, g_xh);

    zero_kernel<<<2048, 256>>>(out, out_size);
    reset_kernel<<<1, 32>>>();
    cvt16_kernel<<<1024, 256>>>(x, xh, (size_t)NTOK * HDIM);
    transcvt_w1<<<dim3(FDIM / 32, HDIM / 32, NE), dim3(32, 8)>>>(w1);
    transcvt_w2<<<dim3(HDIM / 32, FDIM / 32, NE), dim3(32, 8)>>>(w2);
    router_kernel<<<NTOK / 8, 256>>>(x, gw);
    finalize_kernel<<<1, 256>>>(out, out_size);
    gemm1_kernel<<<dim3(FDIM / BN, NTOK / BM, NE), 128, DYN_SMEM>>>(b1);
    gemm2_kernel<<<dim3(HDIM / BN, NTOK / BM, NE), 128, DYN_SMEM>>>(b2, out);
}

// round 14
// speedup vs baseline: 5.1716x; 1.2415x over previous
#include <cuda_runtime.h>
#include <cuda_fp16.h>
#include <math.h>
#include <stdint.h>

#define NTOK 4096
#define HDIM 1024
#define FDIM 4096
#define NE   8

#define BM 128
#define BN 128
#define BK 32
#define NSTAGE 4
#define AW 20                              // words per A row (32 halves + pad)
#define BW 68                              // words per B k-row (128 halves + pad)
#define A_WORDS (BM * AW)                  // 2560
#define B_WORDS (BK * BW)                  // 2176
#define STAGE_WORDS (A_WORDS + B_WORDS)    // 4736 (18944 B)
#define DYN_SMEM (NSTAGE * STAGE_WORDS * 4)  // 75776 bytes

// ---------------- device scratch ----------------
__device__ int   g_count[NE];
__device__ int   g_off[NE];
__device__ int   g_tok[NE * NTOK];
__device__ float g_wt[NE * NTOK];
__device__ float g_zsq[NTOK];
__device__ float g_wa[NTOK];
__device__ float g_wb[NTOK];
__device__ float g_ma[NTOK];
__device__ float g_mb[NTOK];
__device__ float g_part[16 * 5];
__device__ __align__(16) __half g_h1f[(size_t)2 * NTOK * FDIM];   // 64 MiB
__device__ __align__(16) __half g_xh[(size_t)NTOK * HDIM];        // 8 MiB
__device__ __align__(16) __half g_w1h[(size_t)NE * HDIM * FDIM];  // 64 MiB: [E][H][F]
__device__ __align__(16) __half g_w2h[(size_t)NE * FDIM * HDIM];  // 64 MiB: [E][F][H]

// ---------------- helpers ----------------
__device__ __forceinline__ unsigned su32(const void* p) {
    return (unsigned)__cvta_generic_to_shared(p);
}
__device__ __forceinline__ void cp_async16(unsigned dst, const void* src) {
    asm volatile("cp.async.cg.shared.global [%0], [%1], 16;" :: "r"(dst), "l"(src));
}
__device__ __forceinline__ void cp_commit() {
    asm volatile("cp.async.commit_group;" ::: "memory");
}
template<int N> __device__ __forceinline__ void cp_wait() {
    asm volatile("cp.async.wait_group %0;" :: "n"(N) : "memory");
}
__device__ __forceinline__ void ldsm4(unsigned* r, unsigned a) {
    asm volatile("ldmatrix.sync.aligned.m8n8.x4.shared.b16 {%0,%1,%2,%3}, [%4];"
                 : "=r"(r[0]), "=r"(r[1]), "=r"(r[2]), "=r"(r[3]) : "r"(a));
}
__device__ __forceinline__ void ldsm4t(unsigned* r, unsigned a) {
    asm volatile("ldmatrix.sync.aligned.m8n8.x4.trans.shared.b16 {%0,%1,%2,%3}, [%4];"
                 : "=r"(r[0]), "=r"(r[1]), "=r"(r[2]), "=r"(r[3]) : "r"(a));
}
__device__ __forceinline__ void mma16(float* d, const unsigned* a, const unsigned* b) {
    asm volatile(
        "mma.sync.aligned.m16n8k16.row.col.f32.f16.f16.f32 "
        "{%0,%1,%2,%3}, {%4,%5,%6,%7}, {%8,%9}, {%0,%1,%2,%3};"
        : "+f"(d[0]), "+f"(d[1]), "+f"(d[2]), "+f"(d[3])
        : "r"(a[0]), "r"(a[1]), "r"(a[2]), "r"(a[3]), "r"(b[0]), "r"(b[1]));
}
__device__ __forceinline__ float silu_f(float v) { return v / (1.0f + expf(-v)); }

// ---------------- small kernels ----------------
__global__ void zero_kernel(float* out, int n) {
    for (int i = blockIdx.x * blockDim.x + threadIdx.x; i < n; i += gridDim.x * blockDim.x)
        out[i] = 0.0f;
}
__global__ void reset_kernel() {
    if (threadIdx.x < NE) g_count[threadIdx.x] = 0;
}
__global__ void cvt16_kernel(const float* __restrict__ in, __half* __restrict__ out, size_t n) {
    size_t i0 = ((size_t)blockIdx.x * blockDim.x + threadIdx.x) * 8;
    size_t stride = (size_t)gridDim.x * blockDim.x * 8;
    for (size_t i = i0; i < n; i += stride) {
        float4 v = *(const float4*)(in + i);
        float4 u = *(const float4*)(in + i + 4);
        __half2 h0 = __floats2half2_rn(v.x, v.y);
        __half2 h1 = __floats2half2_rn(v.z, v.w);
        __half2 h2 = __floats2half2_rn(u.x, u.y);
        __half2 h3 = __floats2half2_rn(u.z, u.w);
        uint4 o;
        o.x = *(unsigned*)&h0; o.y = *(unsigned*)&h1;
        o.z = *(unsigned*)&h2; o.w = *(unsigned*)&h3;
        *(uint4*)(out + i) = o;
    }
}

// router: one warp per token
__global__ void router_kernel(const float* __restrict__ x, const float* __restrict__ gw) {
    int warp = threadIdx.x >> 5;
    int lane = threadIdx.x & 31;
    int t = blockIdx.x * (blockDim.x >> 5) + warp;
    if (t >= NTOK) return;

    float p[NE];
#pragma unroll
    for (int e = 0; e < NE; e++) p[e] = 0.0f;
    const float* xr = x + (size_t)t * HDIM;
    for (int h = lane; h < HDIM; h += 32) {
        float xv = xr[h];
#pragma unroll
        for (int e = 0; e < NE; e++) p[e] += xv * gw[e * HDIM + h];
    }
#pragma unroll
    for (int e = 0; e < NE; e++) {
#pragma unroll
        for (int s = 16; s > 0; s >>= 1) p[e] += __shfl_xor_sync(0xffffffffu, p[e], s);
    }
    if (lane == 0) {
        float m = p[0];
#pragma unroll
        for (int e = 1; e < NE; e++) m = fmaxf(m, p[e]);
        float Z = 0.0f; float pr[NE];
#pragma unroll
        for (int e = 0; e < NE; e++) { pr[e] = expf(p[e] - m); Z += pr[e]; }
        float invZ = 1.0f / Z;
#pragma unroll
        for (int e = 0; e < NE; e++) pr[e] *= invZ;
        int e1 = 0; float v1 = pr[0];
#pragma unroll
        for (int e = 1; e < NE; e++) if (pr[e] > v1) { v1 = pr[e]; e1 = e; }
        int e2 = -1; float v2 = -1.0f;
#pragma unroll
        for (int e = 0; e < NE; e++) if (e != e1 && pr[e] > v2) { v2 = pr[e]; e2 = e; }
        float s = v1 + v2;
        float lse = m + logf(Z);
        g_zsq[t] = lse * lse;
        g_wa[t] = v1; g_wb[t] = v2;
        g_ma[t] = (e1 == 0 || e2 == 0) ? 1.0f : 0.0f;
        g_mb[t] = (e1 == 1 || e2 == 1) ? 1.0f : 0.0f;
        int s1 = atomicAdd(&g_count[e1], 1);
        g_tok[e1 * NTOK + s1] = t; g_wt[e1 * NTOK + s1] = v1 / s;
        int s2 = atomicAdd(&g_count[e2], 1);
        g_tok[e2 * NTOK + s2] = t; g_wt[e2 * NTOK + s2] = v2 / s;
    }
}

// stage 1: 16 blocks of deterministic partial sums
__global__ void partial_kernel() {
    int tid = threadIdx.x, blk = blockIdx.x;
    float s[5] = {0, 0, 0, 0, 0};
    for (int i = blk * 256 + tid; i < NTOK; i += 16 * 256) {
        s[0] += g_zsq[i]; s[1] += g_wa[i]; s[2] += g_wb[i];
        s[3] += g_ma[i];  s[4] += g_mb[i];
    }
    __shared__ float red[256];
#pragma unroll
    for (int q = 0; q < 5; q++) {
        red[tid] = s[q];
        __syncthreads();
        for (int st = 128; st > 0; st >>= 1) {
            if (tid < st) red[tid] += red[tid + st];
            __syncthreads();
        }
        if (tid == 0) g_part[blk * 5 + q] = red[0];
        __syncthreads();
    }
}

// stage 2: one warp reduces partials, emits losses + offsets
__global__ void finalize_kernel(float* out, int out_size) {
    if (threadIdx.x == 0) {
        float tot[5] = {0, 0, 0, 0, 0};
        for (int b = 0; b < 16; b++)
#pragma unroll
            for (int q = 0; q < 5; q++) tot[q] += g_part[b * 5 + q];
        const float invT = 1.0f / (float)NTOK;
        float zl  = tot[0] * invT;
        float aux = 2.0f * ((tot[3] * invT) * (tot[1] * invT) +
                            (tot[4] * invT) * (tot[2] * invT));
        long long base = (long long)NTOK * HDIM;
        if ((long long)out_size > base)     out[base]     = zl;
        if ((long long)out_size > base + 1) out[base + 1] = aux;
        int o = 0;
        for (int e = 0; e < NE; e++) { g_off[e] = o; o += g_count[e]; }
    }
}

// =====================================================================
// fp16 mma.sync grouped GEMMs. Block 128x128xBK32, 4 warps (2x2),
// warp tile 64x64, m16n8k16, ldmatrix fragment loads, 4-stage cp.async.
// A smem: [BM][AW] k-major (LDSM non-trans). B smem: [BK][BW] n-contig
// k-rows straight from global [k][n] (LDSM .trans). Both conflict-free.
// =====================================================================

// GEMM1: h1f[off+m][n] = fp16(silu( sum_k xh[tok[m]][k] * w1h[e][k][n] + b1[e][n] ))
__global__ void __launch_bounds__(128, 2)
gemm1_kernel(const float* __restrict__ b1) {
    int e = blockIdx.z;
    int cnt = g_count[e];
    int m0 = blockIdx.y * BM;
    if (m0 >= cnt) return;
    int n0 = blockIdx.x * BN;
    int off = g_off[e];

    extern __shared__ unsigned smw[];
    __shared__ int toks[BM];

    int tid = threadIdx.x;
    int wid = tid >> 5, lane = tid & 31;

    if (tid < BM) {
        int r = m0 + tid; if (r > cnt - 1) r = cnt - 1;
        toks[tid] = g_tok[e * NTOK + r];
    }
    __syncthreads();

    unsigned sbase = su32(smw);
    // cp.async slots: 4 A + 4 B chunks of 16B per thread per stage
    unsigned adst[4], bdst[4];
    const char* asrc[4];
    const char* bsrc[4];
#pragma unroll
    for (int j = 0; j < 4; j++) {
        int idx = tid + 128 * j;
        int arow = idx >> 2, ach = idx & 3;         // A: 128 rows x 4 chunks
        adst[j] = sbase + (arow * AW + ach * 4) * 4;
        asrc[j] = (const char*)(g_xh + (size_t)toks[arow] * HDIM) + ach * 16;
        int brow = idx >> 4, bch = idx & 15;        // B: 32 k-rows x 16 chunks
        bdst[j] = sbase + (A_WORDS + brow * BW + bch * 4) * 4;
        bsrc[j] = (const char*)(g_w1h + (size_t)e * HDIM * FDIM + (size_t)brow * FDIM + n0) + bch * 16;
    }
    const size_t aadv = (size_t)BK * 2;             // 64 B per kt
    const size_t badv = (size_t)BK * FDIM * 2;      // B k-rows advance

    int wm = wid >> 1, wn = wid & 1;
    int t8 = lane >> 3, rit = lane & 7;
    // ldmatrix per-lane byte offsets within a stage
    unsigned a_lane = ((wm * 64 + (t8 & 1) * 8 + rit) * AW + (t8 >> 1) * 4) * 4;
    unsigned b_lane = A_WORDS * 4 + ((t8 & 1) * 8 + rit) * (BW * 4) + (wn * 64 + (t8 >> 1) * 8) * 2;

    float acc[4][8][4];
#pragma unroll
    for (int i = 0; i < 4; i++)
#pragma unroll
        for (int j = 0; j < 8; j++)
#pragma unroll
            for (int q = 0; q < 4; q++) acc[i][j][q] = 0.0f;

    const int NKT = HDIM / BK;  // 32
#pragma unroll
    for (int s = 0; s < NSTAGE - 1; s++) {
        unsigned so = s * STAGE_WORDS * 4;
#pragma unroll
        for (int j = 0; j < 4; j++) {
            cp_async16(adst[j] + so, asrc[j] + (size_t)s * aadv);
            cp_async16(bdst[j] + so, bsrc[j] + (size_t)s * badv);
        }
        cp_commit();
    }

    int r = lane >> 2, c = lane & 3;

    for (int kt = 0; kt < NKT; kt++) {
        if (kt < NKT - 2) cp_wait<2>();
        else if (kt == NKT - 2) cp_wait<1>();
        else cp_wait<0>();
        __syncthreads();

        if (kt + 3 < NKT) {
            unsigned so = ((kt + 3) % NSTAGE) * STAGE_WORDS * 4;
            size_t ka = (size_t)(kt + 3) * aadv;
            size_t kb = (size_t)(kt + 3) * badv;
#pragma unroll
            for (int j = 0; j < 4; j++) {
                cp_async16(adst[j] + so, asrc[j] + ka);
                cp_async16(bdst[j] + so, bsrc[j] + kb);
            }
            cp_commit();
        }

        unsigned sb = sbase + (kt % NSTAGE) * STAGE_WORDS * 4;
#pragma unroll
        for (int ks = 0; ks < 2; ks++) {
            unsigned af[4][4], bf[8][2];
#pragma unroll
            for (int i = 0; i < 4; i++)
                ldsm4(af[i], sb + a_lane + (i * 16 * AW + ks * 8) * 4);
#pragma unroll
            for (int jp = 0; jp < 4; jp++) {
                unsigned rr[4];
                ldsm4t(rr, sb + b_lane + ks * 16 * (BW * 4) + jp * 32);
                bf[2 * jp][0] = rr[0]; bf[2 * jp][1] = rr[1];
                bf[2 * jp + 1][0] = rr[2]; bf[2 * jp + 1][1] = rr[3];
            }
#pragma unroll
            for (int i = 0; i < 4; i++)
#pragma unroll
                for (int j = 0; j < 8; j++) mma16(acc[i][j], af[i], bf[j]);
        }
    }

    // epilogue: bias + silu -> fp16
#pragma unroll
    for (int i = 0; i < 4; i++) {
        int mrowA = m0 + wm * 64 + i * 16 + r;
        int mrowB = mrowA + 8;
#pragma unroll
        for (int j = 0; j < 8; j++) {
            int ncol = n0 + wn * 64 + j * 8 + c * 2;
            float2 bb = *(const float2*)&b1[(size_t)e * FDIM + ncol];
            if (mrowA < cnt) {
                __half2 h = __floats2half2_rn(silu_f(acc[i][j][0] + bb.x),
                                              silu_f(acc[i][j][1] + bb.y));
                *(__half2*)&g_h1f[(size_t)(off + mrowA) * FDIM + ncol] = h;
            }
            if (mrowB < cnt) {
                __half2 h = __floats2half2_rn(silu_f(acc[i][j][2] + bb.x),
                                              silu_f(acc[i][j][3] + bb.y));
                *(__half2*)&g_h1f[(size_t)(off + mrowB) * FDIM + ncol] = h;
            }
        }
    }
}

// GEMM2: out[tok[m]][n] += wt[m] * ( sum_k h1f[off+m][k] * w2h[e][k][n] + b2[e][n] )
__global__ void __launch_bounds__(128, 2)
gemm2_kernel(const float* __restrict__ b2, float* __restrict__ out) {
    int e = blockIdx.z;
    int cnt = g_count[e];
    int m0 = blockIdx.y * BM;
    if (m0 >= cnt) return;
    int n0 = blockIdx.x * BN;
    int off = g_off[e];

    extern __shared__ unsigned smw[];
    __shared__ int tks[BM];
    __shared__ float wts[BM];

    int tid = threadIdx.x;
    int wid = tid >> 5, lane = tid & 31;

    if (tid < BM) {
        int r = m0 + tid; if (r > cnt - 1) r = cnt - 1;
        tks[tid] = g_tok[e * NTOK + r];
        wts[tid] = g_wt[e * NTOK + r];
    }
    __syncthreads();

    unsigned sbase = su32(smw);
    unsigned adst[4], bdst[4];
    const char* asrc[4];
    const char* bsrc[4];
#pragma unroll
    for (int j = 0; j < 4; j++) {
        int idx = tid + 128 * j;
        int arow = idx >> 2, ach = idx & 3;
        int rr = m0 + arow; if (rr > cnt - 1) rr = cnt - 1;
        adst[j] = sbase + (arow * AW + ach * 4) * 4;
        asrc[j] = (const char*)(g_h1f + (size_t)(off + rr) * FDIM) + ach * 16;
        int brow = idx >> 4, bch = idx & 15;
        bdst[j] = sbase + (A_WORDS + brow * BW + bch * 4) * 4;
        bsrc[j] = (const char*)(g_w2h + (size_t)e * FDIM * HDIM + (size_t)brow * HDIM + n0) + bch * 16;
    }
    const size_t aadv = (size_t)BK * 2;
    const size_t badv = (size_t)BK * HDIM * 2;

    int wm = wid >> 1, wn = wid & 1;
    int t8 = lane >> 3, rit = lane & 7;
    unsigned a_lane = ((wm * 64 + (t8 & 1) * 8 + rit) * AW + (t8 >> 1) * 4) * 4;
    unsigned b_lane = A_WORDS * 4 + ((t8 & 1) * 8 + rit) * (BW * 4) + (wn * 64 + (t8 >> 1) * 8) * 2;

    float acc[4][8][4];
#pragma unroll
    for (int i = 0; i < 4; i++)
#pragma unroll
        for (int j = 0; j < 8; j++)
#pragma unroll
            for (int q = 0; q < 4; q++) acc[i][j][q] = 0.0f;

    const int NKT = FDIM / BK;  // 128
#pragma unroll
    for (int s = 0; s < NSTAGE - 1; s++) {
        unsigned so = s * STAGE_WORDS * 4;
#pragma unroll
        for (int j = 0; j < 4; j++) {
            cp_async16(adst[j] + so, asrc[j] + (size_t)s * aadv);
            cp_async16(bdst[j] + so, bsrc[j] + (size_t)s * badv);
        }
        cp_commit();
    }

    int r = lane >> 2, c = lane & 3;

    for (int kt = 0; kt < NKT; kt++) {
        if (kt < NKT - 2) cp_wait<2>();
        else if (kt == NKT - 2) cp_wait<1>();
        else cp_wait<0>();
        __syncthreads();

        if (kt + 3 < NKT) {
            unsigned so = ((kt + 3) % NSTAGE) * STAGE_WORDS * 4;
            size_t ka = (size_t)(kt + 3) * aadv;
            size_t kb = (size_t)(kt + 3) * badv;
#pragma unroll
            for (int j = 0; j < 4; j++) {
                cp_async16(adst[j] + so, asrc[j] + ka);
                cp_async16(bdst[j] + so, bsrc[j] + kb);
            }
            cp_commit();
        }

        unsigned sb = sbase + (kt % NSTAGE) * STAGE_WORDS * 4;
#pragma unroll
        for (int ks = 0; ks < 2; ks++) {
            unsigned af[4][4], bf[8][2];
#pragma unroll
            for (int i = 0; i < 4; i++)
                ldsm4(af[i], sb + a_lane + (i * 16 * AW + ks * 8) * 4);
#pragma unroll
            for (int jp = 0; jp < 4; jp++) {
                unsigned rr[4];
                ldsm4t(rr, sb + b_lane + ks * 16 * (BW * 4) + jp * 32);
                bf[2 * jp][0] = rr[0]; bf[2 * jp][1] = rr[1];
                bf[2 * jp + 1][0] = rr[2]; bf[2 * jp + 1][1] = rr[3];
            }
#pragma unroll
            for (int i = 0; i < 4; i++)
#pragma unroll
                for (int j = 0; j < 8; j++) mma16(acc[i][j], af[i], bf[j]);
        }
    }

#pragma unroll
    for (int i = 0; i < 4; i++) {
        int lrowA = wm * 64 + i * 16 + r;
        int lrowB = lrowA + 8;
        int mrowA = m0 + lrowA, mrowB = m0 + lrowB;
#pragma unroll
        for (int j = 0; j < 8; j++) {
            int ncol = n0 + wn * 64 + j * 8 + c * 2;
            float2 bb = *(const float2*)&b2[(size_t)e * HDIM + ncol];
            if (mrowA < cnt) {
                float w = wts[lrowA];
                float* op = out + (size_t)tks[lrowA] * HDIM + ncol;
                atomicAdd(op + 0, w * (acc[i][j][0] + bb.x));
                atomicAdd(op + 1, w * (acc[i][j][1] + bb.y));
            }
            if (mrowB < cnt) {
                float w = wts[lrowB];
                float* op = out + (size_t)tks[lrowB] * HDIM + ncol;
                atomicAdd(op + 0, w * (acc[i][j][2] + bb.x));
                atomicAdd(op + 1, w * (acc[i][j][3] + bb.y));
            }
        }
    }
}

// ---------------- launch ----------------
extern "C" void kernel_launch(void* const* d_in, const int* in_sizes, int n_in,
                              void* d_out, int out_size) {
    const float* x  = (const float*)d_in[0];
    const float* gw = (const float*)d_in[1];
    const float* w1 = (const float*)d_in[2];
    const float* b1 = (const float*)d_in[3];
    const float* w2 = (const float*)d_in[4];
    const float* b2 = (const float*)d_in[5];
    float* out = (float*)d_out;

    cudaFuncSetAttribute(gemm1_kernel, cudaFuncAttributeMaxDynamicSharedMemorySize, DYN_SMEM);
    cudaFuncSetAttribute(gemm2_kernel, cudaFuncAttributeMaxDynamicSharedMemorySize, DYN_SMEM);

    __half* xh;  cudaGetSymbolAddress((void**)&xh,  g_xh);
    __half* w1h; cudaGetSymbolAddress((void**)&w1h, g_w1h);
    __half* w2h; cudaGetSymbolAddress((void**)&w2h, g_w2h);

    zero_kernel<<<2048, 256>>>(out, out_size);
    reset_kernel<<<1, 32>>>();
    cvt16_kernel<<<1024, 256>>>(x, xh, (size_t)NTOK * HDIM);
    cvt16_kernel<<<4096, 256>>>(w1, w1h, (size_t)NE * HDIM * FDIM);
    cvt16_kernel<<<4096, 256>>>(w2, w2h, (size_t)NE * FDIM * HDIM);
    router_kernel<<<NTOK / 8, 256>>>(x, gw);
    partial_kernel<<<16, 256>>>();
    finalize_kernel<<<1, 32>>>(out, out_size);
    gemm1_kernel<<<dim3(FDIM / BN, NTOK / BM, NE), 128, DYN_SMEM>>>(b1);
    gemm2_kernel<<<dim3(HDIM / BN, NTOK / BM, NE), 128, DYN_SMEM>>>(b2, out);
}